// round 1
// baseline (speedup 1.0000x reference)
#include <cuda_runtime.h>
#include <math.h>

#define N_NODES 100000
#define N_EDGES 1600000
#define D 128
#define NG 64
#define DD 512
#define DH2 256
#define NCLS 16

// ---------------- scratch (static device globals; no allocation) ----------------
__device__ float g_bufA[(size_t)N_NODES * D];   // layer input (LN output)
__device__ float g_bufG[(size_t)N_NODES * D];   // g = (in @ W) * dinv_row
__device__ int   g_deg[N_NODES];
__device__ float g_dinv[N_NODES];
__device__ int   g_rowptr[N_NODES + 1];
__device__ int   g_cursor[N_NODES];
__device__ int   g_csr_src[N_EDGES];
__device__ int   g_blocksum[128];
__device__ int   g_blockoff[128];
__device__ int   g_flags[2];                    // [0]=edge nonzero-odd-word, [1]=batch
__device__ int   g_gstart[NG + 1];
__device__ float g_pooled[NG * D];
__device__ float g_z1[NG * DD];
__device__ float g_z2[NG * DH2];

// ---------------- helpers ----------------
__device__ __forceinline__ int fetchIdx(const void* p, long long i, int is64) {
    if (is64) return (int)((const long long*)p)[i];
    return ((const int*)p)[i];
}

// ---------------- init / dtype detection ----------------
__global__ void init_kernel() {
    int i = blockIdx.x * blockDim.x + threadIdx.x;
    for (; i < N_NODES; i += gridDim.x * blockDim.x) g_deg[i] = 0;
    if (blockIdx.x == 0 && threadIdx.x < 2) g_flags[threadIdx.x] = 0;
}

// Scan odd 32-bit words within the first n words (safe for either dtype).
// If the underlying data is int64 (values < 2^31, >=0), all odd words are 0.
__global__ void detect_kernel(const unsigned* ew, int ne, const unsigned* bw, int nb) {
    int stride = gridDim.x * blockDim.x;
    int tid = blockIdx.x * blockDim.x + threadIdx.x;
    int f0 = 0, f1 = 0;
    for (int i = tid; i < ne / 2; i += stride) if (ew[2 * i + 1] != 0u) { f0 = 1; break; }
    for (int i = tid; i < nb / 2; i += stride) if (bw[2 * i + 1] != 0u) { f1 = 1; break; }
    if (f0) atomicOr(&g_flags[0], 1);
    if (f1) atomicOr(&g_flags[1], 1);
}

// ---------------- CSR build ----------------
__global__ void deg_kernel(const void* eidx) {
    int is64 = (g_flags[0] == 0);
    for (long long e = blockIdx.x * blockDim.x + threadIdx.x; e < N_EDGES;
         e += (long long)gridDim.x * blockDim.x) {
        int dst = fetchIdx(eidx, (long long)N_EDGES + e, is64);
        atomicAdd(&g_deg[dst], 1);
    }
}

__global__ void dinv_kernel() {
    int i = blockIdx.x * blockDim.x + threadIdx.x;
    if (i < N_NODES) g_dinv[i] = rsqrtf((float)(g_deg[i] + 1));
}

__global__ void scan_local() {  // 1024 threads/block
    __shared__ int sm[1024];
    int t = threadIdx.x;
    int i = blockIdx.x * 1024 + t;
    int v = (i < N_NODES) ? g_deg[i] : 0;
    sm[t] = v;
    __syncthreads();
    for (int o = 1; o < 1024; o <<= 1) {
        int add = 0;
        if (t >= o) add = sm[t - o];
        __syncthreads();
        if (t >= o) sm[t] += add;
        __syncthreads();
    }
    int incl = sm[t];
    if (i < N_NODES) g_rowptr[i] = incl - v;  // local exclusive
    if (t == 1023) g_blocksum[blockIdx.x] = incl;
}

__global__ void scan_block() {  // 1 thread
    int off = 0;
    for (int b = 0; b < (N_NODES + 1023) / 1024; b++) {
        g_blockoff[b] = off;
        off += g_blocksum[b];
    }
}

__global__ void scan_add() {
    int i = blockIdx.x * blockDim.x + threadIdx.x;
    if (i < N_NODES) {
        int val = g_rowptr[i] + g_blockoff[i >> 10];
        g_rowptr[i] = val;
        g_cursor[i] = val;
    }
    if (i == 0) g_rowptr[N_NODES] = N_EDGES;
}

__global__ void scatter_kernel(const void* eidx) {
    int is64 = (g_flags[0] == 0);
    for (long long e = blockIdx.x * blockDim.x + threadIdx.x; e < N_EDGES;
         e += (long long)gridDim.x * blockDim.x) {
        int src = fetchIdx(eidx, e, is64);
        int dst = fetchIdx(eidx, (long long)N_EDGES + e, is64);
        int p = atomicAdd(&g_cursor[dst], 1);
        g_csr_src[p] = src;
    }
}

// ---------------- GEMM: g = (A @ W) * dinv_row ----------------
// BM=128 rows/block, 256 threads, K chunked by 32. fp32 SIMT register tiling.
__global__ void __launch_bounds__(256) gemm_scale_kernel(const float* __restrict__ X,
                                                         int useX,
                                                         const float* __restrict__ W) {
    __shared__ float As[32][132];  // [k][row], padded
    __shared__ float Ws[32][128];  // [k][col]
    const float* A = useX ? X : g_bufA;
    int tid = threadIdx.x;
    int tx = tid & 31, ty = tid >> 5;  // ty: 0..7
    int R0 = blockIdx.x * 128;
    float acc[16][4];
#pragma unroll
    for (int i = 0; i < 16; i++)
#pragma unroll
        for (int j = 0; j < 4; j++) acc[i][j] = 0.f;

    for (int kc = 0; kc < D; kc += 32) {
        // load A chunk (128 rows x 32 cols) transposed into As
#pragma unroll
        for (int l = 0; l < 4; l++) {
            int idx = tid + l * 256;     // 0..1023 float4 slots
            int c4 = idx & 7;            // 0..7  (float4 column within chunk)
            int r = idx >> 3;            // 0..127
            int gr = R0 + r;
            if (gr >= N_NODES) gr = N_NODES - 1;
            float4 v = *(const float4*)(A + (long long)gr * D + kc + c4 * 4);
            As[c4 * 4 + 0][r] = v.x;
            As[c4 * 4 + 1][r] = v.y;
            As[c4 * 4 + 2][r] = v.z;
            As[c4 * 4 + 3][r] = v.w;
        }
        // load W chunk (32 x 128)
#pragma unroll
        for (int l = 0; l < 4; l++) {
            int idx = tid + l * 256;     // 0..1023 float4 slots
            int kk = idx >> 5;           // 0..31
            int cc = (idx & 31) * 4;
            float4 v = *(const float4*)(W + (long long)(kc + kk) * D + cc);
            *(float4*)&Ws[kk][cc] = v;
        }
        __syncthreads();
#pragma unroll
        for (int k = 0; k < 32; k++) {
            float a[16];
#pragma unroll
            for (int i = 0; i < 16; i += 4) {
                float4 v = *(const float4*)&As[k][ty * 16 + i];
                a[i] = v.x; a[i + 1] = v.y; a[i + 2] = v.z; a[i + 3] = v.w;
            }
            float4 w = *(const float4*)&Ws[k][tx * 4];
#pragma unroll
            for (int i = 0; i < 16; i++) {
                acc[i][0] += a[i] * w.x;
                acc[i][1] += a[i] * w.y;
                acc[i][2] += a[i] * w.z;
                acc[i][3] += a[i] * w.w;
            }
        }
        __syncthreads();
    }
#pragma unroll
    for (int i = 0; i < 16; i++) {
        int gr = R0 + ty * 16 + i;
        if (gr < N_NODES) {
            float s = g_dinv[gr];
            float4 o;
            o.x = acc[i][0] * s; o.y = acc[i][1] * s;
            o.z = acc[i][2] * s; o.w = acc[i][3] * s;
            *(float4*)(g_bufG + (long long)gr * D + tx * 4) = o;
        }
    }
}

// ---------------- Aggregate + bias + (emb) + ReLU + LayerNorm ----------------
// one warp per node, 4 features per lane (float4)
__global__ void __launch_bounds__(256) agg_ln_kernel(const float* __restrict__ bias,
                                                     const float* __restrict__ gamma,
                                                     const float* __restrict__ beta,
                                                     float* __restrict__ emb, int writeEmb) {
    int warp = (blockIdx.x * blockDim.x + threadIdx.x) >> 5;
    int lane = threadIdx.x & 31;
    if (warp >= N_NODES) return;
    int node = warp;
    const float4* gp = (const float4*)g_bufG;
    float4 acc = gp[(long long)node * 32 + lane];  // self-loop term g_i
    int beg = g_rowptr[node], end = g_rowptr[node + 1];
    int j = beg;
    for (; j + 1 < end; j += 2) {
        int s0 = g_csr_src[j];
        int s1 = g_csr_src[j + 1];
        float4 v0 = gp[(long long)s0 * 32 + lane];
        float4 v1 = gp[(long long)s1 * 32 + lane];
        acc.x += v0.x + v1.x; acc.y += v0.y + v1.y;
        acc.z += v0.z + v1.z; acc.w += v0.w + v1.w;
    }
    if (j < end) {
        int s0 = g_csr_src[j];
        float4 v0 = gp[(long long)s0 * 32 + lane];
        acc.x += v0.x; acc.y += v0.y; acc.z += v0.z; acc.w += v0.w;
    }
    float di = g_dinv[node];
    float4 b4 = ((const float4*)bias)[lane];
    float4 conv;
    conv.x = di * acc.x + b4.x; conv.y = di * acc.y + b4.y;
    conv.z = di * acc.z + b4.z; conv.w = di * acc.w + b4.w;
    if (writeEmb) ((float4*)emb)[(long long)node * 32 + lane] = conv;
    float4 r;
    r.x = fmaxf(conv.x, 0.f); r.y = fmaxf(conv.y, 0.f);
    r.z = fmaxf(conv.z, 0.f); r.w = fmaxf(conv.w, 0.f);
    float s = r.x + r.y + r.z + r.w;
#pragma unroll
    for (int o = 16; o > 0; o >>= 1) s += __shfl_xor_sync(0xffffffffu, s, o);
    float mean = s * (1.0f / 128.0f);
    float dx = r.x - mean, dy = r.y - mean, dz = r.z - mean, dw = r.w - mean;
    float q = dx * dx + dy * dy + dz * dz + dw * dw;
#pragma unroll
    for (int o = 16; o > 0; o >>= 1) q += __shfl_xor_sync(0xffffffffu, q, o);
    float inv = rsqrtf(q * (1.0f / 128.0f) + 1e-5f);
    float4 gm = ((const float4*)gamma)[lane];
    float4 bt = ((const float4*)beta)[lane];
    float4 y;
    y.x = dx * inv * gm.x + bt.x; y.y = dy * inv * gm.y + bt.y;
    y.z = dz * inv * gm.z + bt.z; y.w = dw * inv * gm.w + bt.w;
    ((float4*)g_bufA)[(long long)node * 32 + lane] = y;
}

// ---------------- pooling ----------------
__global__ void gstart_kernel(const void* batch) {
    int t = threadIdx.x;
    if (t > NG) return;
    int is64 = (g_flags[1] == 0);
    int lo = 0, hi = N_NODES;  // first i with batch[i] >= t
    while (lo < hi) {
        int mid = (lo + hi) >> 1;
        int v = fetchIdx(batch, mid, is64);
        if (v < t) lo = mid + 1; else hi = mid;
    }
    g_gstart[t] = lo;
}

__global__ void pool_kernel() {  // 64 blocks x 128 threads
    int gph = blockIdx.x, t = threadIdx.x;
    int s = g_gstart[gph], e = g_gstart[gph + 1];
    float a0 = 0.f, a1 = 0.f, a2 = 0.f, a3 = 0.f;
    int i = s;
    for (; i + 3 < e; i += 4) {
        a0 += g_bufA[(long long)i * D + t];
        a1 += g_bufA[(long long)(i + 1) * D + t];
        a2 += g_bufA[(long long)(i + 2) * D + t];
        a3 += g_bufA[(long long)(i + 3) * D + t];
    }
    for (; i < e; i++) a0 += g_bufA[(long long)i * D + t];
    float acc = (a0 + a1) + (a2 + a3);
    float cnt = (float)(e - s);
    g_pooled[gph * D + t] = acc / fmaxf(cnt, 1.0f);
}

// ---------------- MLP head ----------------
__global__ void mlp1_kernel(const float* __restrict__ W1, const float* __restrict__ b1) {
    __shared__ float sp[D];
    int gph = blockIdx.x, t = threadIdx.x;  // 512 threads
    if (t < D) sp[t] = g_pooled[gph * D + t];
    __syncthreads();
    float acc = b1[t];
    for (int k = 0; k < D; k++) acc += sp[k] * W1[k * DD + t];
    g_z1[gph * DD + t] = acc;
}

__global__ void mlp2_kernel(const float* __restrict__ W2, const float* __restrict__ b2) {
    __shared__ float sp[DD];
    int gph = blockIdx.x, t = threadIdx.x;  // 256 threads
    sp[t] = g_z1[gph * DD + t];
    sp[t + 256] = g_z1[gph * DD + t + 256];
    __syncthreads();
    float acc = b2[t];
    for (int k = 0; k < DD; k++) acc += sp[k] * W2[k * DH2 + t];
    g_z2[gph * DH2 + t] = acc;
}

__global__ void mlp3_kernel(const float* __restrict__ W3, const float* __restrict__ b3,
                            float* __restrict__ out) {
    __shared__ float sp[DH2];
    __shared__ float z[NCLS];
    int gph = blockIdx.x, t = threadIdx.x;  // 32 threads
    for (int i = t; i < DH2; i += 32) sp[i] = g_z2[gph * DH2 + i];
    __syncwarp();
    if (t < NCLS) {
        float acc = b3[t];
        for (int k = 0; k < DH2; k++) acc += sp[k] * W3[k * NCLS + t];
        z[t] = acc;
    }
    __syncwarp();
    if (t < NCLS) {
        float m = -1e30f;
        for (int i = 0; i < NCLS; i++) m = fmaxf(m, z[i]);
        float sum = 0.f;
        for (int i = 0; i < NCLS; i++) sum += expf(z[i] - m);
        out[(long long)N_NODES * D + gph * NCLS + t] = z[t] - m - logf(sum);
    }
}

// ---------------- launch ----------------
extern "C" void kernel_launch(void* const* d_in, const int* in_sizes, int n_in,
                              void* d_out, int out_size) {
    const float* x = (const float*)d_in[0];
    const void* eidx = d_in[1];
    // d_in[2] = edge_attr (unused by reference)
    const void* batch = d_in[3];
    const float* W0 = (const float*)d_in[4];
    const float* b0 = (const float*)d_in[5];
    const float* convW = (const float*)d_in[6];
    const float* convB = (const float*)d_in[7];
    const float* lng = (const float*)d_in[8];
    const float* lnb = (const float*)d_in[9];
    const float* W1 = (const float*)d_in[10];
    const float* b1 = (const float*)d_in[11];
    const float* W2 = (const float*)d_in[12];
    const float* b2 = (const float*)d_in[13];
    const float* W3 = (const float*)d_in[14];
    const float* b3 = (const float*)d_in[15];
    float* out = (float*)d_out;

    init_kernel<<<256, 256>>>();
    detect_kernel<<<512, 256>>>((const unsigned*)eidx, in_sizes[1],
                                (const unsigned*)batch, in_sizes[3]);
    deg_kernel<<<2048, 256>>>(eidx);
    dinv_kernel<<<(N_NODES + 255) / 256, 256>>>();
    scan_local<<<(N_NODES + 1023) / 1024, 1024>>>();
    scan_block<<<1, 1>>>();
    scan_add<<<(N_NODES + 255) / 256, 256>>>();
    scatter_kernel<<<2048, 256>>>(eidx);

    for (int L = 0; L < 4; L++) {
        const float* W = (L == 0) ? W0 : convW + (size_t)(L - 1) * D * D;
        const float* bias = (L == 0) ? b0 : convB + (size_t)(L - 1) * D;
        const float* gamma = lng + (size_t)L * D;
        const float* beta = lnb + (size_t)L * D;
        gemm_scale_kernel<<<(N_NODES + 127) / 128, 256>>>(x, (L == 0) ? 1 : 0, W);
        agg_ln_kernel<<<(N_NODES + 7) / 8, 256>>>(bias, gamma, beta, out, (L == 3) ? 1 : 0);
    }

    gstart_kernel<<<1, 128>>>(batch);
    pool_kernel<<<NG, 128>>>();
    mlp1_kernel<<<NG, DD>>>(W1, b1);
    mlp2_kernel<<<NG, DH2>>>(W2, b2);
    mlp3_kernel<<<NG, 32>>>(W3, b3, out);
}

// round 3
// speedup vs baseline: 1.1311x; 1.1311x over previous
#include <cuda_runtime.h>
#include <cuda_bf16.h>
#include <math.h>
#include <stdint.h>

#define N_NODES 100000
#define N_EDGES 1600000
#define D 128
#define NG 64
#define DD 512
#define DH2 256
#define NCLS 16

// ---------------- scratch (static device globals; no allocation) ----------------
__device__ float g_bufA[(size_t)N_NODES * D];   // layer input (LN output)
__device__ float g_bufG[(size_t)N_NODES * D];   // g = (in @ W) * dinv_row
__device__ int   g_deg[N_NODES];
__device__ float g_dinv[N_NODES];
__device__ int   g_rowptr[N_NODES + 1];
__device__ int   g_cursor[N_NODES];
__device__ int   g_csr_src[N_EDGES];
__device__ int   g_blocksum[128];
__device__ int   g_blockoff[128];
__device__ int   g_flags[2];                    // [0]=edge nonzero-odd-word, [1]=batch
__device__ int   g_gstart[NG + 1];
__device__ float g_pooled[NG * D];
__device__ float g_z1[NG * DD];
__device__ float g_z2[NG * DH2];

// ---------------- helpers ----------------
__device__ __forceinline__ int fetchIdx(const void* p, long long i, int is64) {
    if (is64) return (int)((const long long*)p)[i];
    return ((const int*)p)[i];
}

// ---------------- init / dtype detection ----------------
__global__ void init_kernel() {
    int i = blockIdx.x * blockDim.x + threadIdx.x;
    for (; i < N_NODES; i += gridDim.x * blockDim.x) g_deg[i] = 0;
    if (blockIdx.x == 0 && threadIdx.x < 2) g_flags[threadIdx.x] = 0;
}

__global__ void detect_kernel(const unsigned* ew, int ne, const unsigned* bw, int nb) {
    int stride = gridDim.x * blockDim.x;
    int tid = blockIdx.x * blockDim.x + threadIdx.x;
    int f0 = 0, f1 = 0;
    for (int i = tid; i < ne / 2; i += stride) if (ew[2 * i + 1] != 0u) { f0 = 1; break; }
    for (int i = tid; i < nb / 2; i += stride) if (bw[2 * i + 1] != 0u) { f1 = 1; break; }
    if (f0) atomicOr(&g_flags[0], 1);
    if (f1) atomicOr(&g_flags[1], 1);
}

// ---------------- CSR build ----------------
__global__ void deg_kernel(const void* eidx) {
    int is64 = (g_flags[0] == 0);
    for (long long e = blockIdx.x * blockDim.x + threadIdx.x; e < N_EDGES;
         e += (long long)gridDim.x * blockDim.x) {
        int dst = fetchIdx(eidx, (long long)N_EDGES + e, is64);
        atomicAdd(&g_deg[dst], 1);
    }
}

__global__ void dinv_kernel() {
    int i = blockIdx.x * blockDim.x + threadIdx.x;
    if (i < N_NODES) g_dinv[i] = rsqrtf((float)(g_deg[i] + 1));
}

__global__ void scan_local() {  // 1024 threads/block
    __shared__ int sm[1024];
    int t = threadIdx.x;
    int i = blockIdx.x * 1024 + t;
    int v = (i < N_NODES) ? g_deg[i] : 0;
    sm[t] = v;
    __syncthreads();
    for (int o = 1; o < 1024; o <<= 1) {
        int add = 0;
        if (t >= o) add = sm[t - o];
        __syncthreads();
        if (t >= o) sm[t] += add;
        __syncthreads();
    }
    int incl = sm[t];
    if (i < N_NODES) g_rowptr[i] = incl - v;  // local exclusive
    if (t == 1023) g_blocksum[blockIdx.x] = incl;
}

__global__ void scan_block() {  // 1 thread
    int off = 0;
    for (int b = 0; b < (N_NODES + 1023) / 1024; b++) {
        g_blockoff[b] = off;
        off += g_blocksum[b];
    }
}

__global__ void scan_add() {
    int i = blockIdx.x * blockDim.x + threadIdx.x;
    if (i < N_NODES) {
        int val = g_rowptr[i] + g_blockoff[i >> 10];
        g_rowptr[i] = val;
        g_cursor[i] = val;
    }
    if (i == 0) g_rowptr[N_NODES] = N_EDGES;
}

__global__ void scatter_kernel(const void* eidx) {
    int is64 = (g_flags[0] == 0);
    for (long long e = blockIdx.x * blockDim.x + threadIdx.x; e < N_EDGES;
         e += (long long)gridDim.x * blockDim.x) {
        int src = fetchIdx(eidx, e, is64);
        int dst = fetchIdx(eidx, (long long)N_EDGES + e, is64);
        int p = atomicAdd(&g_cursor[dst], 1);
        g_csr_src[p] = src;
    }
}

// ---------------- GEMM: g = (A @ W) * dinv_row  (mma.sync bf16, 2-way split) ----------------
// CTA: 128 rows x 128 cols x K=128. 8 warps in 4(M) x 2(N); warp tile 32x64.
// smem: Ahi/Alo [128][132] bf16, Bhi/Blo [128(n)][132] bf16 (W transposed).
// 3 MMAs per fragment pair: Ah*Bh + Ah*Bl + Al*Bh (lo*lo dropped, ~2^-34).
#define SROW 132
#define AH_OFF 0
#define AL_OFF 33792
#define BH_OFF 67584
#define BL_OFF 101376
#define GEMM_SMEM 135168

__device__ __forceinline__ void mma_bf16(float* c, const uint32_t* a, const uint32_t* b) {
    asm volatile(
        "mma.sync.aligned.m16n8k16.row.col.f32.bf16.bf16.f32 "
        "{%0,%1,%2,%3}, {%4,%5,%6,%7}, {%8,%9}, {%0,%1,%2,%3};"
        : "+f"(c[0]), "+f"(c[1]), "+f"(c[2]), "+f"(c[3])
        : "r"(a[0]), "r"(a[1]), "r"(a[2]), "r"(a[3]), "r"(b[0]), "r"(b[1]));
}

__global__ void __launch_bounds__(256) gemm_bf16_kernel(const float* __restrict__ X,
                                                        int useX,
                                                        const float* __restrict__ W) {
    extern __shared__ char sm[];
    const float* A = useX ? X : g_bufA;
    int tid = threadIdx.x;
    long long R0 = (long long)blockIdx.x * 128;

    // ---- load A tile [128 x 128] f32, split to bf16 hi/lo ----
#pragma unroll
    for (int l = 0; l < 16; l++) {
        int idx = tid + l * 256;
        int r = idx >> 5;
        int k = (idx & 31) * 4;
        long long gr = R0 + r;
        if (gr >= N_NODES) gr = N_NODES - 1;
        float4 v = *(const float4*)(A + gr * D + k);
        __nv_bfloat16 h0 = __float2bfloat16_rn(v.x);
        __nv_bfloat16 h1 = __float2bfloat16_rn(v.y);
        __nv_bfloat16 h2 = __float2bfloat16_rn(v.z);
        __nv_bfloat16 h3 = __float2bfloat16_rn(v.w);
        __nv_bfloat16 l0 = __float2bfloat16_rn(v.x - __bfloat162float(h0));
        __nv_bfloat16 l1 = __float2bfloat16_rn(v.y - __bfloat162float(h1));
        __nv_bfloat16 l2 = __float2bfloat16_rn(v.z - __bfloat162float(h2));
        __nv_bfloat16 l3 = __float2bfloat16_rn(v.w - __bfloat162float(h3));
        int off = (r * SROW + k) * 2;
        *(__nv_bfloat162*)(sm + AH_OFF + off) = __nv_bfloat162(h0, h1);
        *(__nv_bfloat162*)(sm + AH_OFF + off + 4) = __nv_bfloat162(h2, h3);
        *(__nv_bfloat162*)(sm + AL_OFF + off) = __nv_bfloat162(l0, l1);
        *(__nv_bfloat162*)(sm + AL_OFF + off + 4) = __nv_bfloat162(l2, l3);
    }
    // ---- load W [128k x 128n], transposed into Bs[n][k], split hi/lo ----
    {
        int n = tid & 127;
        int k0 = (tid >> 7) * 64;
#pragma unroll 8
        for (int kk = 0; kk < 64; kk++) {
            int k = k0 + kk;
            float wv = W[(size_t)k * D + n];
            __nv_bfloat16 h = __float2bfloat16_rn(wv);
            __nv_bfloat16 lo = __float2bfloat16_rn(wv - __bfloat162float(h));
            ((__nv_bfloat16*)(sm + BH_OFF))[n * SROW + k] = h;
            ((__nv_bfloat16*)(sm + BL_OFF))[n * SROW + k] = lo;
        }
    }
    __syncthreads();

    // ---- compute ----
    int wid = tid >> 5, lane = tid & 31;
    int g = lane >> 2, t = lane & 3;
    int warpM = wid >> 1, warpN = wid & 1;

    float C[2][8][4];
#pragma unroll
    for (int mf = 0; mf < 2; mf++)
#pragma unroll
        for (int nf = 0; nf < 8; nf++)
#pragma unroll
            for (int j = 0; j < 4; j++) C[mf][nf][j] = 0.f;

#pragma unroll
    for (int ks = 0; ks < 8; ks++) {
        int kb = ks * 16;
        uint32_t bh[8][2], bl[8][2];
#pragma unroll
        for (int nf = 0; nf < 8; nf++) {
            int n = warpN * 64 + nf * 8 + g;
            int off = (n * SROW + kb + t * 2) * 2;
            bh[nf][0] = *(const uint32_t*)(sm + BH_OFF + off);
            bh[nf][1] = *(const uint32_t*)(sm + BH_OFF + off + 16);
            bl[nf][0] = *(const uint32_t*)(sm + BL_OFF + off);
            bl[nf][1] = *(const uint32_t*)(sm + BL_OFF + off + 16);
        }
#pragma unroll
        for (int mf = 0; mf < 2; mf++) {
            int r = warpM * 32 + mf * 16 + g;
            int off = (r * SROW + kb + t * 2) * 2;
            uint32_t ah[4], al[4];
            ah[0] = *(const uint32_t*)(sm + AH_OFF + off);
            ah[1] = *(const uint32_t*)(sm + AH_OFF + off + 8 * SROW * 2);
            ah[2] = *(const uint32_t*)(sm + AH_OFF + off + 16);
            ah[3] = *(const uint32_t*)(sm + AH_OFF + off + 8 * SROW * 2 + 16);
            al[0] = *(const uint32_t*)(sm + AL_OFF + off);
            al[1] = *(const uint32_t*)(sm + AL_OFF + off + 8 * SROW * 2);
            al[2] = *(const uint32_t*)(sm + AL_OFF + off + 16);
            al[3] = *(const uint32_t*)(sm + AL_OFF + off + 8 * SROW * 2 + 16);
#pragma unroll
            for (int nf = 0; nf < 8; nf++) {
                mma_bf16(C[mf][nf], ah, bh[nf]);
                mma_bf16(C[mf][nf], ah, bl[nf]);
                mma_bf16(C[mf][nf], al, bh[nf]);
            }
        }
    }

    // ---- epilogue: scale by dinv, store float2 ----
#pragma unroll
    for (int mf = 0; mf < 2; mf++) {
        long long r0 = R0 + warpM * 32 + mf * 16 + g;
        long long r1 = r0 + 8;
        float d0 = (r0 < N_NODES) ? g_dinv[r0] : 0.f;
        float d1 = (r1 < N_NODES) ? g_dinv[r1] : 0.f;
#pragma unroll
        for (int nf = 0; nf < 8; nf++) {
            int col = warpN * 64 + nf * 8 + t * 2;
            if (r0 < N_NODES) {
                float2 o;
                o.x = C[mf][nf][0] * d0;
                o.y = C[mf][nf][1] * d0;
                *(float2*)(g_bufG + r0 * D + col) = o;
            }
            if (r1 < N_NODES) {
                float2 o;
                o.x = C[mf][nf][2] * d1;
                o.y = C[mf][nf][3] * d1;
                *(float2*)(g_bufG + r1 * D + col) = o;
            }
        }
    }
}

// ---------------- Aggregate + bias + (emb) + ReLU + LayerNorm ----------------
// one warp per node, 4 features per lane (float4)
__global__ void __launch_bounds__(256) agg_ln_kernel(const float* __restrict__ bias,
                                                     const float* __restrict__ gamma,
                                                     const float* __restrict__ beta,
                                                     float* __restrict__ emb, int writeEmb) {
    int warp = (blockIdx.x * blockDim.x + threadIdx.x) >> 5;
    int lane = threadIdx.x & 31;
    if (warp >= N_NODES) return;
    int node = warp;
    const float4* gp = (const float4*)g_bufG;
    float4 acc = gp[(long long)node * 32 + lane];  // self-loop term g_i
    int beg = g_rowptr[node], end = g_rowptr[node + 1];
    int j = beg;
    for (; j + 1 < end; j += 2) {
        int s0 = g_csr_src[j];
        int s1 = g_csr_src[j + 1];
        float4 v0 = gp[(long long)s0 * 32 + lane];
        float4 v1 = gp[(long long)s1 * 32 + lane];
        acc.x += v0.x + v1.x; acc.y += v0.y + v1.y;
        acc.z += v0.z + v1.z; acc.w += v0.w + v1.w;
    }
    if (j < end) {
        int s0 = g_csr_src[j];
        float4 v0 = gp[(long long)s0 * 32 + lane];
        acc.x += v0.x; acc.y += v0.y; acc.z += v0.z; acc.w += v0.w;
    }
    float di = g_dinv[node];
    float4 b4 = ((const float4*)bias)[lane];
    float4 conv;
    conv.x = di * acc.x + b4.x; conv.y = di * acc.y + b4.y;
    conv.z = di * acc.z + b4.z; conv.w = di * acc.w + b4.w;
    if (writeEmb) ((float4*)emb)[(long long)node * 32 + lane] = conv;
    float4 r;
    r.x = fmaxf(conv.x, 0.f); r.y = fmaxf(conv.y, 0.f);
    r.z = fmaxf(conv.z, 0.f); r.w = fmaxf(conv.w, 0.f);
    float s = r.x + r.y + r.z + r.w;
#pragma unroll
    for (int o = 16; o > 0; o >>= 1) s += __shfl_xor_sync(0xffffffffu, s, o);
    float mean = s * (1.0f / 128.0f);
    float dx = r.x - mean, dy = r.y - mean, dz = r.z - mean, dw = r.w - mean;
    float q = dx * dx + dy * dy + dz * dz + dw * dw;
#pragma unroll
    for (int o = 16; o > 0; o >>= 1) q += __shfl_xor_sync(0xffffffffu, q, o);
    float inv = rsqrtf(q * (1.0f / 128.0f) + 1e-5f);
    float4 gm = ((const float4*)gamma)[lane];
    float4 bt = ((const float4*)beta)[lane];
    float4 y;
    y.x = dx * inv * gm.x + bt.x; y.y = dy * inv * gm.y + bt.y;
    y.z = dz * inv * gm.z + bt.z; y.w = dw * inv * gm.w + bt.w;
    ((float4*)g_bufA)[(long long)node * 32 + lane] = y;
}

// ---------------- pooling ----------------
__global__ void gstart_kernel(const void* batch) {
    int t = threadIdx.x;
    if (t > NG) return;
    int is64 = (g_flags[1] == 0);
    int lo = 0, hi = N_NODES;  // first i with batch[i] >= t
    while (lo < hi) {
        int mid = (lo + hi) >> 1;
        int v = fetchIdx(batch, mid, is64);
        if (v < t) lo = mid + 1; else hi = mid;
    }
    g_gstart[t] = lo;
}

__global__ void pool_kernel() {  // 64 blocks x 128 threads
    int gph = blockIdx.x, t = threadIdx.x;
    int s = g_gstart[gph], e = g_gstart[gph + 1];
    float a0 = 0.f, a1 = 0.f, a2 = 0.f, a3 = 0.f;
    int i = s;
    for (; i + 3 < e; i += 4) {
        a0 += g_bufA[(long long)i * D + t];
        a1 += g_bufA[(long long)(i + 1) * D + t];
        a2 += g_bufA[(long long)(i + 2) * D + t];
        a3 += g_bufA[(long long)(i + 3) * D + t];
    }
    for (; i < e; i++) a0 += g_bufA[(long long)i * D + t];
    float acc = (a0 + a1) + (a2 + a3);
    float cnt = (float)(e - s);
    g_pooled[gph * D + t] = acc / fmaxf(cnt, 1.0f);
}

// ---------------- MLP head ----------------
__global__ void mlp1_kernel(const float* __restrict__ W1, const float* __restrict__ b1) {
    __shared__ float sp[D];
    int gph = blockIdx.x, t = threadIdx.x;  // 512 threads
    if (t < D) sp[t] = g_pooled[gph * D + t];
    __syncthreads();
    float acc = b1[t];
    for (int k = 0; k < D; k++) acc += sp[k] * W1[k * DD + t];
    g_z1[gph * DD + t] = acc;
}

__global__ void mlp2_kernel(const float* __restrict__ W2, const float* __restrict__ b2) {
    __shared__ float sp[DD];
    int gph = blockIdx.x, t = threadIdx.x;  // 256 threads
    sp[t] = g_z1[gph * DD + t];
    sp[t + 256] = g_z1[gph * DD + t + 256];
    __syncthreads();
    float acc = b2[t];
    for (int k = 0; k < DD; k++) acc += sp[k] * W2[k * DH2 + t];
    g_z2[gph * DH2 + t] = acc;
}

__global__ void mlp3_kernel(const float* __restrict__ W3, const float* __restrict__ b3,
                            float* __restrict__ out) {
    __shared__ float sp[DH2];
    __shared__ float z[NCLS];
    int gph = blockIdx.x, t = threadIdx.x;  // 32 threads
    for (int i = t; i < DH2; i += 32) sp[i] = g_z2[gph * DH2 + i];
    __syncwarp();
    if (t < NCLS) {
        float acc = b3[t];
        for (int k = 0; k < DH2; k++) acc += sp[k] * W3[k * NCLS + t];
        z[t] = acc;
    }
    __syncwarp();
    if (t < NCLS) {
        float m = -1e30f;
        for (int i = 0; i < NCLS; i++) m = fmaxf(m, z[i]);
        float sum = 0.f;
        for (int i = 0; i < NCLS; i++) sum += expf(z[i] - m);
        out[(long long)N_NODES * D + gph * NCLS + t] = z[t] - m - logf(sum);
    }
}

// ---------------- launch ----------------
extern "C" void kernel_launch(void* const* d_in, const int* in_sizes, int n_in,
                              void* d_out, int out_size) {
    const float* x = (const float*)d_in[0];
    const void* eidx = d_in[1];
    // d_in[2] = edge_attr (unused by reference)
    const void* batch = d_in[3];
    const float* W0 = (const float*)d_in[4];
    const float* b0 = (const float*)d_in[5];
    const float* convW = (const float*)d_in[6];
    const float* convB = (const float*)d_in[7];
    const float* lng = (const float*)d_in[8];
    const float* lnb = (const float*)d_in[9];
    const float* W1 = (const float*)d_in[10];
    const float* b1 = (const float*)d_in[11];
    const float* W2 = (const float*)d_in[12];
    const float* b2 = (const float*)d_in[13];
    const float* W3 = (const float*)d_in[14];
    const float* b3 = (const float*)d_in[15];
    float* out = (float*)d_out;

    static int s_attr_done = 0;
    if (!s_attr_done) {
        cudaFuncSetAttribute(gemm_bf16_kernel, cudaFuncAttributeMaxDynamicSharedMemorySize,
                             GEMM_SMEM);
        s_attr_done = 1;
    }

    init_kernel<<<256, 256>>>();
    detect_kernel<<<512, 256>>>((const unsigned*)eidx, in_sizes[1],
                                (const unsigned*)batch, in_sizes[3]);
    deg_kernel<<<2048, 256>>>(eidx);
    dinv_kernel<<<(N_NODES + 255) / 256, 256>>>();
    scan_local<<<(N_NODES + 1023) / 1024, 1024>>>();
    scan_block<<<1, 1>>>();
    scan_add<<<(N_NODES + 255) / 256, 256>>>();
    scatter_kernel<<<2048, 256>>>(eidx);

    for (int L = 0; L < 4; L++) {
        const float* W = (L == 0) ? W0 : convW + (size_t)(L - 1) * D * D;
        const float* bias = (L == 0) ? b0 : convB + (size_t)(L - 1) * D;
        const float* gamma = lng + (size_t)L * D;
        const float* beta = lnb + (size_t)L * D;
        gemm_bf16_kernel<<<(N_NODES + 127) / 128, 256, GEMM_SMEM>>>(x, (L == 0) ? 1 : 0, W);
        agg_ln_kernel<<<(N_NODES + 7) / 8, 256>>>(bias, gamma, beta, out, (L == 3) ? 1 : 0);
    }

    gstart_kernel<<<1, 128>>>(batch);
    pool_kernel<<<NG, 128>>>();
    mlp1_kernel<<<NG, DD>>>(W1, b1);
    mlp2_kernel<<<NG, DD / 2>>>(W2, b2);
    mlp3_kernel<<<NG, 32>>>(W3, b3, out);
}

// round 4
// speedup vs baseline: 1.1570x; 1.0229x over previous
#include <cuda_runtime.h>
#include <cuda_bf16.h>
#include <cuda_fp16.h>
#include <math.h>
#include <stdint.h>

#define N_NODES 100000
#define N_EDGES 1600000
#define D 128
#define NG 64
#define DD 512
#define DH2 256
#define NCLS 16

// ---------------- scratch (static device globals; no allocation) ----------------
__device__ float  g_bufA[(size_t)N_NODES * D];   // layer input (LN output), fp32
__device__ __half g_bufG[(size_t)N_NODES * D];   // g = (in @ W) * dinv_row, fp16 (gather buffer)
__device__ int    g_deg[N_NODES];
__device__ float  g_dinv[N_NODES];
__device__ int    g_rowptr[N_NODES + 1];
__device__ int    g_cursor[N_NODES];
__device__ int    g_csr_src[N_EDGES];
__device__ int    g_blocksum[128];
__device__ int    g_blockoff[128];
__device__ int    g_flags[2];                    // [0]=edge nonzero-odd-word, [1]=batch
__device__ __nv_bfloat16 g_Whi[4 * D * D];       // pre-split W, [L][n][k] (transposed)
__device__ __nv_bfloat16 g_Wlo[4 * D * D];

// ---------------- helpers ----------------
__device__ __forceinline__ int fetchIdx(const void* p, long long i, int is64) {
    if (is64) return (int)((const long long*)p)[i];
    return ((const int*)p)[i];
}

// ---------------- init / dtype detection ----------------
__global__ void init_kernel() {
    int i = blockIdx.x * blockDim.x + threadIdx.x;
    for (; i < N_NODES; i += gridDim.x * blockDim.x) g_deg[i] = 0;
    if (blockIdx.x == 0 && threadIdx.x < 2) g_flags[threadIdx.x] = 0;
}

__global__ void detect_kernel(const unsigned* ew, int ne, const unsigned* bw, int nb) {
    int stride = gridDim.x * blockDim.x;
    int tid = blockIdx.x * blockDim.x + threadIdx.x;
    int f0 = 0, f1 = 0;
    for (int i = tid; i < ne / 2; i += stride) if (ew[2 * i + 1] != 0u) { f0 = 1; break; }
    for (int i = tid; i < nb / 2; i += stride) if (bw[2 * i + 1] != 0u) { f1 = 1; break; }
    if (f0) atomicOr(&g_flags[0], 1);
    if (f1) atomicOr(&g_flags[1], 1);
}

// ---------------- CSR build ----------------
__global__ void deg_kernel(const void* eidx) {
    int is64 = (g_flags[0] == 0);
    for (long long e = blockIdx.x * blockDim.x + threadIdx.x; e < N_EDGES;
         e += (long long)gridDim.x * blockDim.x) {
        int dst = fetchIdx(eidx, (long long)N_EDGES + e, is64);
        atomicAdd(&g_deg[dst], 1);
    }
}

__global__ void scan_local() {  // 1024 threads/block; also writes dinv
    __shared__ int sm[1024];
    int t = threadIdx.x;
    int i = blockIdx.x * 1024 + t;
    int v = (i < N_NODES) ? g_deg[i] : 0;
    if (i < N_NODES) g_dinv[i] = rsqrtf((float)(v + 1));
    sm[t] = v;
    __syncthreads();
    for (int o = 1; o < 1024; o <<= 1) {
        int add = 0;
        if (t >= o) add = sm[t - o];
        __syncthreads();
        if (t >= o) sm[t] += add;
        __syncthreads();
    }
    int incl = sm[t];
    if (i < N_NODES) g_rowptr[i] = incl - v;  // local exclusive
    if (t == 1023) g_blocksum[blockIdx.x] = incl;
}

__global__ void scan_block() {  // 1 thread
    int off = 0;
    for (int b = 0; b < (N_NODES + 1023) / 1024; b++) {
        g_blockoff[b] = off;
        off += g_blocksum[b];
    }
}

__global__ void scan_add() {
    int i = blockIdx.x * blockDim.x + threadIdx.x;
    if (i < N_NODES) {
        int val = g_rowptr[i] + g_blockoff[i >> 10];
        g_rowptr[i] = val;
        g_cursor[i] = val;
    }
    if (i == 0) g_rowptr[N_NODES] = N_EDGES;
}

__global__ void scatter_kernel(const void* eidx) {
    int is64 = (g_flags[0] == 0);
    for (long long e = blockIdx.x * blockDim.x + threadIdx.x; e < N_EDGES;
         e += (long long)gridDim.x * blockDim.x) {
        int src = fetchIdx(eidx, e, is64);
        int dst = fetchIdx(eidx, (long long)N_EDGES + e, is64);
        int p = atomicAdd(&g_cursor[dst], 1);
        g_csr_src[p] = src;
    }
}

// ---------------- W pre-split: g_W{hi,lo}[L][n][k] = split(W_L[k][n]) ----------------
__global__ void wsplit_kernel(const float* __restrict__ W0, const float* __restrict__ convW) {
    int idx = blockIdx.x * blockDim.x + threadIdx.x;  // 0 .. 4*16384-1
    if (idx >= 4 * D * D) return;
    int L = idx >> 14;
    int r = (idx >> 7) & 127;  // k (row of W)
    int c = idx & 127;         // n (col of W)
    float wv = (L == 0) ? W0[r * D + c] : convW[(size_t)(L - 1) * D * D + r * D + c];
    __nv_bfloat16 h = __float2bfloat16_rn(wv);
    __nv_bfloat16 lo = __float2bfloat16_rn(wv - __bfloat162float(h));
    g_Whi[L * D * D + c * D + r] = h;   // transposed [n][k]
    g_Wlo[L * D * D + c * D + r] = lo;
}

// ---------------- GEMM: g = (A @ W) * dinv_row  (mma.sync bf16, 2-way split) ----------------
#define SROW 132
#define AH_OFF 0
#define AL_OFF 33792
#define BH_OFF 67584
#define BL_OFF 101376
#define GEMM_SMEM 135168

__device__ __forceinline__ void mma_bf16(float* c, const uint32_t* a, const uint32_t* b) {
    asm volatile(
        "mma.sync.aligned.m16n8k16.row.col.f32.bf16.bf16.f32 "
        "{%0,%1,%2,%3}, {%4,%5,%6,%7}, {%8,%9}, {%0,%1,%2,%3};"
        : "+f"(c[0]), "+f"(c[1]), "+f"(c[2]), "+f"(c[3])
        : "r"(a[0]), "r"(a[1]), "r"(a[2]), "r"(a[3]), "r"(b[0]), "r"(b[1]));
}

__global__ void __launch_bounds__(256) gemm_bf16_kernel(const float* __restrict__ X,
                                                        int useX, int L) {
    extern __shared__ char sm[];
    const float* A = useX ? X : g_bufA;
    int tid = threadIdx.x;
    long long R0 = (long long)blockIdx.x * 128;

    // ---- load A tile [128 x 128] f32, split to bf16 hi/lo ----
#pragma unroll
    for (int l = 0; l < 16; l++) {
        int idx = tid + l * 256;
        int r = idx >> 5;
        int k = (idx & 31) * 4;
        long long gr = R0 + r;
        if (gr >= N_NODES) gr = N_NODES - 1;
        float4 v = *(const float4*)(A + gr * D + k);
        __nv_bfloat16 h0 = __float2bfloat16_rn(v.x);
        __nv_bfloat16 h1 = __float2bfloat16_rn(v.y);
        __nv_bfloat16 h2 = __float2bfloat16_rn(v.z);
        __nv_bfloat16 h3 = __float2bfloat16_rn(v.w);
        __nv_bfloat16 l0 = __float2bfloat16_rn(v.x - __bfloat162float(h0));
        __nv_bfloat16 l1 = __float2bfloat16_rn(v.y - __bfloat162float(h1));
        __nv_bfloat16 l2 = __float2bfloat16_rn(v.z - __bfloat162float(h2));
        __nv_bfloat16 l3 = __float2bfloat16_rn(v.w - __bfloat162float(h3));
        int off = (r * SROW + k) * 2;
        *(__nv_bfloat162*)(sm + AH_OFF + off) = __nv_bfloat162(h0, h1);
        *(__nv_bfloat162*)(sm + AH_OFF + off + 4) = __nv_bfloat162(h2, h3);
        *(__nv_bfloat162*)(sm + AL_OFF + off) = __nv_bfloat162(l0, l1);
        *(__nv_bfloat162*)(sm + AL_OFF + off + 4) = __nv_bfloat162(l2, l3);
    }
    // ---- copy pre-split W tiles: Bs[n][k] from g_W{hi,lo}[L] ----
    {
        int n = tid >> 1;
        int khalf = (tid & 1) * 64;
        const uint2* srcH = (const uint2*)(g_Whi + (size_t)L * D * D + n * D + khalf);
        const uint2* srcL = (const uint2*)(g_Wlo + (size_t)L * D * D + n * D + khalf);
        char* dH = sm + BH_OFF + (n * SROW + khalf) * 2;
        char* dL = sm + BL_OFF + (n * SROW + khalf) * 2;
#pragma unroll
        for (int j = 0; j < 16; j++) {
            *(uint2*)(dH + j * 8) = srcH[j];
            *(uint2*)(dL + j * 8) = srcL[j];
        }
    }
    __syncthreads();

    // ---- compute ----
    int wid = tid >> 5, lane = tid & 31;
    int g = lane >> 2, t = lane & 3;
    int warpM = wid >> 1, warpN = wid & 1;

    float C[2][8][4];
#pragma unroll
    for (int mf = 0; mf < 2; mf++)
#pragma unroll
        for (int nf = 0; nf < 8; nf++)
#pragma unroll
            for (int j = 0; j < 4; j++) C[mf][nf][j] = 0.f;

#pragma unroll
    for (int ks = 0; ks < 8; ks++) {
        int kb = ks * 16;
        uint32_t bh[8][2], bl[8][2];
#pragma unroll
        for (int nf = 0; nf < 8; nf++) {
            int n = warpN * 64 + nf * 8 + g;
            int off = (n * SROW + kb + t * 2) * 2;
            bh[nf][0] = *(const uint32_t*)(sm + BH_OFF + off);
            bh[nf][1] = *(const uint32_t*)(sm + BH_OFF + off + 16);
            bl[nf][0] = *(const uint32_t*)(sm + BL_OFF + off);
            bl[nf][1] = *(const uint32_t*)(sm + BL_OFF + off + 16);
        }
#pragma unroll
        for (int mf = 0; mf < 2; mf++) {
            int r = warpM * 32 + mf * 16 + g;
            int off = (r * SROW + kb + t * 2) * 2;
            uint32_t ah[4], al[4];
            ah[0] = *(const uint32_t*)(sm + AH_OFF + off);
            ah[1] = *(const uint32_t*)(sm + AH_OFF + off + 8 * SROW * 2);
            ah[2] = *(const uint32_t*)(sm + AH_OFF + off + 16);
            ah[3] = *(const uint32_t*)(sm + AH_OFF + off + 8 * SROW * 2 + 16);
            al[0] = *(const uint32_t*)(sm + AL_OFF + off);
            al[1] = *(const uint32_t*)(sm + AL_OFF + off + 8 * SROW * 2);
            al[2] = *(const uint32_t*)(sm + AL_OFF + off + 16);
            al[3] = *(const uint32_t*)(sm + AL_OFF + off + 8 * SROW * 2 + 16);
#pragma unroll
            for (int nf = 0; nf < 8; nf++) {
                mma_bf16(C[mf][nf], ah, bh[nf]);
                mma_bf16(C[mf][nf], ah, bl[nf]);
                mma_bf16(C[mf][nf], al, bh[nf]);
            }
        }
    }

    // ---- epilogue: scale by dinv, store fp16 ----
#pragma unroll
    for (int mf = 0; mf < 2; mf++) {
        long long r0 = R0 + warpM * 32 + mf * 16 + g;
        long long r1 = r0 + 8;
        float d0 = (r0 < N_NODES) ? g_dinv[r0] : 0.f;
        float d1 = (r1 < N_NODES) ? g_dinv[r1] : 0.f;
#pragma unroll
        for (int nf = 0; nf < 8; nf++) {
            int col = warpN * 64 + nf * 8 + t * 2;
            if (r0 < N_NODES)
                *(__half2*)(g_bufG + r0 * D + col) =
                    __floats2half2_rn(C[mf][nf][0] * d0, C[mf][nf][1] * d0);
            if (r1 < N_NODES)
                *(__half2*)(g_bufG + r1 * D + col) =
                    __floats2half2_rn(C[mf][nf][2] * d1, C[mf][nf][3] * d1);
        }
    }
}

// ---------------- Aggregate + bias + (emb) + ReLU + LayerNorm ----------------
// one warp per node, 4 features per lane; fp16 gather, fp32 accumulate
__global__ void __launch_bounds__(256) agg_ln_kernel(const float* __restrict__ bias,
                                                     const float* __restrict__ gamma,
                                                     const float* __restrict__ beta,
                                                     float* __restrict__ emb, int writeEmb) {
    int warp = (blockIdx.x * blockDim.x + threadIdx.x) >> 5;
    int lane = threadIdx.x & 31;
    if (warp >= N_NODES) return;
    int node = warp;
    const uint2* gp = (const uint2*)g_bufG;  // 4 halves per uint2

    float4 acc;
    {   // self-loop term g_i
        uint2 v = gp[(size_t)node * 32 + lane];
        float2 f01 = __half22float2(*reinterpret_cast<const __half2*>(&v.x));
        float2 f23 = __half22float2(*reinterpret_cast<const __half2*>(&v.y));
        acc.x = f01.x; acc.y = f01.y; acc.z = f23.x; acc.w = f23.y;
    }
    int beg = g_rowptr[node], end = g_rowptr[node + 1];
    int j = beg;
    for (; j + 1 < end; j += 2) {
        int s0 = g_csr_src[j];
        int s1 = g_csr_src[j + 1];
        uint2 v0 = gp[(size_t)s0 * 32 + lane];
        uint2 v1 = gp[(size_t)s1 * 32 + lane];
        float2 a01 = __half22float2(*reinterpret_cast<const __half2*>(&v0.x));
        float2 a23 = __half22float2(*reinterpret_cast<const __half2*>(&v0.y));
        float2 b01 = __half22float2(*reinterpret_cast<const __half2*>(&v1.x));
        float2 b23 = __half22float2(*reinterpret_cast<const __half2*>(&v1.y));
        acc.x += a01.x + b01.x; acc.y += a01.y + b01.y;
        acc.z += a23.x + b23.x; acc.w += a23.y + b23.y;
    }
    if (j < end) {
        int s0 = g_csr_src[j];
        uint2 v0 = gp[(size_t)s0 * 32 + lane];
        float2 a01 = __half22float2(*reinterpret_cast<const __half2*>(&v0.x));
        float2 a23 = __half22float2(*reinterpret_cast<const __half2*>(&v0.y));
        acc.x += a01.x; acc.y += a01.y; acc.z += a23.x; acc.w += a23.y;
    }
    float di = g_dinv[node];
    float4 b4 = ((const float4*)bias)[lane];
    float4 conv;
    conv.x = di * acc.x + b4.x; conv.y = di * acc.y + b4.y;
    conv.z = di * acc.z + b4.z; conv.w = di * acc.w + b4.w;
    if (writeEmb) ((float4*)emb)[(long long)node * 32 + lane] = conv;
    float4 r;
    r.x = fmaxf(conv.x, 0.f); r.y = fmaxf(conv.y, 0.f);
    r.z = fmaxf(conv.z, 0.f); r.w = fmaxf(conv.w, 0.f);
    float s = r.x + r.y + r.z + r.w;
#pragma unroll
    for (int o = 16; o > 0; o >>= 1) s += __shfl_xor_sync(0xffffffffu, s, o);
    float mean = s * (1.0f / 128.0f);
    float dx = r.x - mean, dy = r.y - mean, dz = r.z - mean, dw = r.w - mean;
    float q = dx * dx + dy * dy + dz * dz + dw * dw;
#pragma unroll
    for (int o = 16; o > 0; o >>= 1) q += __shfl_xor_sync(0xffffffffu, q, o);
    float inv = rsqrtf(q * (1.0f / 128.0f) + 1e-5f);
    float4 gm = ((const float4*)gamma)[lane];
    float4 bt = ((const float4*)beta)[lane];
    float4 y;
    y.x = dx * inv * gm.x + bt.x; y.y = dy * inv * gm.y + bt.y;
    y.z = dz * inv * gm.z + bt.z; y.w = dw * inv * gm.w + bt.w;
    ((float4*)g_bufA)[(long long)node * 32 + lane] = y;
}

// ---------------- fused pool + MLP + log_softmax (one block per graph) ----------------
__global__ void __launch_bounds__(512) poolmlp_kernel(
    const void* __restrict__ batch,
    const float* __restrict__ W1, const float* __restrict__ b1,
    const float* __restrict__ W2, const float* __restrict__ b2,
    const float* __restrict__ W3, const float* __restrict__ b3,
    float* __restrict__ out) {
    __shared__ float s_part[4][128];
    __shared__ float s_pool[128];
    __shared__ float s_z1[DD];
    __shared__ float s_z2[DH2];
    __shared__ float s_z[NCLS];
    __shared__ int s_bounds[2];

    int gph = blockIdx.x, t = threadIdx.x;
    if (t < 2) {
        int is64 = (g_flags[1] == 0);
        int target = gph + t;
        int lo = 0, hi = N_NODES;  // first i with batch[i] >= target
        while (lo < hi) {
            int mid = (lo + hi) >> 1;
            int v = fetchIdx(batch, mid, is64);
            if (v < target) lo = mid + 1; else hi = mid;
        }
        s_bounds[t] = lo;
    }
    __syncthreads();
    int s = s_bounds[0], e = s_bounds[1];

    // pooling: 4 row-streams x 128 cols
    {
        int col = t & 127, rq = t >> 7;
        float a = 0.f;
        for (int i = s + rq; i < e; i += 4) a += g_bufA[(long long)i * D + col];
        s_part[rq][col] = a;
    }
    __syncthreads();
    if (t < 128) {
        float cnt = (float)(e - s);
        s_pool[t] = (s_part[0][t] + s_part[1][t] + s_part[2][t] + s_part[3][t]) /
                    fmaxf(cnt, 1.0f);
    }
    __syncthreads();
    // mlp1: 128 -> 512
    {
        float acc = b1[t];
#pragma unroll 8
        for (int k = 0; k < D; k++) acc += s_pool[k] * W1[k * DD + t];
        s_z1[t] = acc;
    }
    __syncthreads();
    // mlp2: 512 -> 256
    if (t < DH2) {
        float acc = b2[t];
#pragma unroll 8
        for (int k = 0; k < DD; k++) acc += s_z1[k] * W2[k * DH2 + t];
        s_z2[t] = acc;
    }
    __syncthreads();
    // mlp3: 256 -> 16
    if (t < NCLS) {
        float acc = b3[t];
#pragma unroll 8
        for (int k = 0; k < DH2; k++) acc += s_z2[k] * W3[k * NCLS + t];
        s_z[t] = acc;
    }
    __syncthreads();
    if (t < NCLS) {
        float m = -1e30f;
        for (int i = 0; i < NCLS; i++) m = fmaxf(m, s_z[i]);
        float sum = 0.f;
        for (int i = 0; i < NCLS; i++) sum += expf(s_z[i] - m);
        out[(long long)N_NODES * D + gph * NCLS + t] = s_z[t] - m - logf(sum);
    }
}

// ---------------- launch ----------------
extern "C" void kernel_launch(void* const* d_in, const int* in_sizes, int n_in,
                              void* d_out, int out_size) {
    const float* x = (const float*)d_in[0];
    const void* eidx = d_in[1];
    // d_in[2] = edge_attr (unused by reference)
    const void* batch = d_in[3];
    const float* W0 = (const float*)d_in[4];
    const float* b0 = (const float*)d_in[5];
    const float* convW = (const float*)d_in[6];
    const float* convB = (const float*)d_in[7];
    const float* lng = (const float*)d_in[8];
    const float* lnb = (const float*)d_in[9];
    const float* W1 = (const float*)d_in[10];
    const float* b1 = (const float*)d_in[11];
    const float* W2 = (const float*)d_in[12];
    const float* b2 = (const float*)d_in[13];
    const float* W3 = (const float*)d_in[14];
    const float* b3 = (const float*)d_in[15];
    float* out = (float*)d_out;

    cudaFuncSetAttribute(gemm_bf16_kernel, cudaFuncAttributeMaxDynamicSharedMemorySize,
                         GEMM_SMEM);

    init_kernel<<<256, 256>>>();
    detect_kernel<<<512, 256>>>((const unsigned*)eidx, in_sizes[1],
                                (const unsigned*)batch, in_sizes[3]);
    deg_kernel<<<2048, 256>>>(eidx);
    scan_local<<<(N_NODES + 1023) / 1024, 1024>>>();
    scan_block<<<1, 1>>>();
    scan_add<<<(N_NODES + 255) / 256, 256>>>();
    scatter_kernel<<<2048, 256>>>(eidx);
    wsplit_kernel<<<(4 * D * D + 255) / 256, 256>>>(W0, convW);

    for (int L = 0; L < 4; L++) {
        const float* bias = (L == 0) ? b0 : convB + (size_t)(L - 1) * D;
        const float* gamma = lng + (size_t)L * D;
        const float* beta = lnb + (size_t)L * D;
        gemm_bf16_kernel<<<(N_NODES + 127) / 128, 256, GEMM_SMEM>>>(x, (L == 0) ? 1 : 0, L);
        agg_ln_kernel<<<(N_NODES + 7) / 8, 256>>>(bias, gamma, beta, out, (L == 3) ? 1 : 0);
    }

    poolmlp_kernel<<<NG, 512>>>(batch, W1, b1, W2, b2, W3, b3, out);
}

// round 6
// speedup vs baseline: 1.3609x; 1.1762x over previous
#include <cuda_runtime.h>
#include <cuda_fp16.h>
#include <math.h>
#include <stdint.h>

#define N_NODES 100000
#define N_EDGES 1600000
#define D 128
#define NG 64
#define DD 512
#define DH2 256
#define NCLS 16

// ---------------- scratch (static device globals; no allocation) ----------------
__device__ __half g_bufA[(size_t)N_NODES * D];   // layer input (LN output), fp16
__device__ __half g_bufG[(size_t)N_NODES * D];   // g = (in @ W) * dinv_row, fp16
__device__ int    g_deg[N_NODES];
__device__ float  g_dinv[N_NODES];
__device__ int    g_rowptr[N_NODES + 1];
__device__ int    g_cursor[N_NODES];
__device__ int    g_csr_src[N_EDGES];
__device__ int    g_blocksum[128];
__device__ int    g_blockoff[128];
__device__ int    g_flags[2];                    // [0]=edge nonzero-odd-word, [1]=batch
__device__ __half g_Whi[4 * D * D];              // pre-split W, [L][n][k] (transposed)
__device__ __half g_Wlo[4 * D * D];

// ---------------- helpers ----------------
__device__ __forceinline__ int fetchIdx(const void* p, long long i, int is64) {
    if (is64) return (int)((const long long*)p)[i];
    return ((const int*)p)[i];
}

// ---------------- init + dtype detection (flags or-accumulate; idempotent) -------
__global__ void init_detect_kernel(const unsigned* ew, int ne, const unsigned* bw, int nb) {
    int stride = gridDim.x * blockDim.x;
    int tid = blockIdx.x * blockDim.x + threadIdx.x;
    for (int i = tid; i < N_NODES; i += stride) g_deg[i] = 0;
    int f0 = 0, f1 = 0;
    for (int i = tid; i < ne / 2; i += stride) if (ew[2 * i + 1] != 0u) { f0 = 1; break; }
    for (int i = tid; i < nb / 2; i += stride) if (bw[2 * i + 1] != 0u) { f1 = 1; break; }
    if (f0) atomicOr(&g_flags[0], 1);
    if (f1) atomicOr(&g_flags[1], 1);
}

// ---------------- CSR build ----------------
__global__ void deg_kernel(const void* eidx) {
    int is64 = (g_flags[0] == 0);
    for (long long e = blockIdx.x * blockDim.x + threadIdx.x; e < N_EDGES;
         e += (long long)gridDim.x * blockDim.x) {
        int dst = fetchIdx(eidx, (long long)N_EDGES + e, is64);
        atomicAdd(&g_deg[dst], 1);
    }
}

__global__ void scan_local() {  // 1024 threads/block; also writes dinv
    __shared__ int sm[1024];
    int t = threadIdx.x;
    int i = blockIdx.x * 1024 + t;
    int v = (i < N_NODES) ? g_deg[i] : 0;
    if (i < N_NODES) g_dinv[i] = rsqrtf((float)(v + 1));
    sm[t] = v;
    __syncthreads();
    for (int o = 1; o < 1024; o <<= 1) {
        int add = 0;
        if (t >= o) add = sm[t - o];
        __syncthreads();
        if (t >= o) sm[t] += add;
        __syncthreads();
    }
    int incl = sm[t];
    if (i < N_NODES) g_rowptr[i] = incl - v;  // local exclusive
    if (t == 1023) g_blocksum[blockIdx.x] = incl;
}

__global__ void scan_block() {  // single block, 128 threads
    __shared__ int s[128];
    int t = threadIdx.x;
    const int nb = (N_NODES + 1023) / 1024;
    int v = (t < nb) ? g_blocksum[t] : 0;
    s[t] = v;
    __syncthreads();
    for (int o = 1; o < 128; o <<= 1) {
        int add = (t >= o) ? s[t - o] : 0;
        __syncthreads();
        s[t] += add;
        __syncthreads();
    }
    if (t < nb) g_blockoff[t] = s[t] - v;  // exclusive
}

__global__ void scan_add() {
    int i = blockIdx.x * blockDim.x + threadIdx.x;
    if (i < N_NODES) {
        int val = g_rowptr[i] + g_blockoff[i >> 10];
        g_rowptr[i] = val;
        g_cursor[i] = val;
    }
    if (i == 0) g_rowptr[N_NODES] = N_EDGES;
}

__global__ void scatter_kernel(const void* eidx) {
    int is64 = (g_flags[0] == 0);
    for (long long e = blockIdx.x * blockDim.x + threadIdx.x; e < N_EDGES;
         e += (long long)gridDim.x * blockDim.x) {
        int src = fetchIdx(eidx, e, is64);
        int dst = fetchIdx(eidx, (long long)N_EDGES + e, is64);
        int p = atomicAdd(&g_cursor[dst], 1);
        g_csr_src[p] = src;
    }
}

// ---------------- W pre-split: g_W{hi,lo}[L][n][k] = fp16 split of W_L[k][n] ------
__global__ void wsplit_kernel(const float* __restrict__ W0, const float* __restrict__ convW) {
    int idx = blockIdx.x * blockDim.x + threadIdx.x;  // 0 .. 4*16384-1
    if (idx >= 4 * D * D) return;
    int L = idx >> 14;
    int r = (idx >> 7) & 127;  // k (row of W)
    int c = idx & 127;         // n (col of W)
    float wv = (L == 0) ? W0[r * D + c] : convW[(size_t)(L - 1) * D * D + r * D + c];
    __half h = __float2half_rn(wv);
    __half lo = __float2half_rn(wv - __half2float(h));
    g_Whi[L * D * D + c * D + r] = h;   // transposed [n][k]
    g_Wlo[L * D * D + c * D + r] = lo;
}

// ---------------- GEMM: g = (A @ W) * dinv_row  (mma.sync fp16, 2 products) ------
// CTA: 128 rows x 128 cols x K=128. 8 warps 4(M)x2(N); warp tile 32x64.
// smem: A fp16 [128][136], Bh/Bl fp16 [128(n)][136]. C = A*Bh + A*Bl.
#define SROW 136
#define A_OFF 0
#define BH_OFF 34816
#define BL_OFF 69632
#define GEMM_SMEM 104448

__device__ __forceinline__ void mma_f16(float* c, const uint32_t* a, const uint32_t* b) {
    asm volatile(
        "mma.sync.aligned.m16n8k16.row.col.f32.f16.f16.f32 "
        "{%0,%1,%2,%3}, {%4,%5,%6,%7}, {%8,%9}, {%0,%1,%2,%3};"
        : "+f"(c[0]), "+f"(c[1]), "+f"(c[2]), "+f"(c[3])
        : "r"(a[0]), "r"(a[1]), "r"(a[2]), "r"(a[3]), "r"(b[0]), "r"(b[1]));
}

__global__ void __launch_bounds__(256, 2) gemm_f16_kernel(const float* __restrict__ Xf,
                                                          int useX, int L) {
    extern __shared__ char sm[];
    int tid = threadIdx.x;
    long long R0 = (long long)blockIdx.x * 128;

    // ---- A fill: row r = tid>>1, 64-col half p = tid&1 ----
    {
        int r = tid >> 1, p = tid & 1;
        long long gr = R0 + r;
        if (gr >= N_NODES) gr = N_NODES - 1;
        char* dst = sm + A_OFF + ((size_t)r * SROW + p * 64) * 2;
        if (useX) {
            const float4* s4 = (const float4*)(Xf + gr * D + p * 64);
#pragma unroll
            for (int j = 0; j < 16; j++) {
                float4 v = s4[j];
                __half2 h01 = __floats2half2_rn(v.x, v.y);
                __half2 h23 = __floats2half2_rn(v.z, v.w);
                *(__half2*)(dst + j * 8) = h01;
                *(__half2*)(dst + j * 8 + 4) = h23;
            }
        } else {
            const uint4* s = (const uint4*)(g_bufA + gr * D + p * 64);
#pragma unroll
            for (int j = 0; j < 8; j++) *(uint4*)(dst + j * 16) = s[j];
        }
    }
    // ---- B fill (pre-split fp16 hi/lo, [n][k] contiguous) ----
    {
        int n = tid >> 1, p = tid & 1;
        const uint4* sH = (const uint4*)(g_Whi + ((size_t)L * D + n) * D + p * 64);
        const uint4* sL = (const uint4*)(g_Wlo + ((size_t)L * D + n) * D + p * 64);
        char* dH = sm + BH_OFF + ((size_t)n * SROW + p * 64) * 2;
        char* dL = sm + BL_OFF + ((size_t)n * SROW + p * 64) * 2;
#pragma unroll
        for (int j = 0; j < 8; j++) {
            *(uint4*)(dH + j * 16) = sH[j];
            *(uint4*)(dL + j * 16) = sL[j];
        }
    }
    __syncthreads();

    // ---- compute ----
    int wid = tid >> 5, lane = tid & 31;
    int g = lane >> 2, t = lane & 3;
    int warpM = wid >> 1, warpN = wid & 1;

    float C[2][8][4];
#pragma unroll
    for (int mf = 0; mf < 2; mf++)
#pragma unroll
        for (int nf = 0; nf < 8; nf++)
#pragma unroll
            for (int j = 0; j < 4; j++) C[mf][nf][j] = 0.f;

#pragma unroll
    for (int ks = 0; ks < 8; ks++) {
        int kb = ks * 16;
        uint32_t bh[8][2], bl[8][2];
#pragma unroll
        for (int nf = 0; nf < 8; nf++) {
            int n = warpN * 64 + nf * 8 + g;
            int off = (n * SROW + kb + t * 2) * 2;
            bh[nf][0] = *(const uint32_t*)(sm + BH_OFF + off);
            bh[nf][1] = *(const uint32_t*)(sm + BH_OFF + off + 16);
            bl[nf][0] = *(const uint32_t*)(sm + BL_OFF + off);
            bl[nf][1] = *(const uint32_t*)(sm + BL_OFF + off + 16);
        }
#pragma unroll
        for (int mf = 0; mf < 2; mf++) {
            int r = warpM * 32 + mf * 16 + g;
            int off = (r * SROW + kb + t * 2) * 2;
            uint32_t a[4];
            a[0] = *(const uint32_t*)(sm + A_OFF + off);
            a[1] = *(const uint32_t*)(sm + A_OFF + off + 8 * SROW * 2);
            a[2] = *(const uint32_t*)(sm + A_OFF + off + 16);
            a[3] = *(const uint32_t*)(sm + A_OFF + off + 8 * SROW * 2 + 16);
#pragma unroll
            for (int nf = 0; nf < 8; nf++) {
                mma_f16(C[mf][nf], a, bh[nf]);
                mma_f16(C[mf][nf], a, bl[nf]);
            }
        }
    }

    // ---- epilogue: scale by dinv, store fp16 ----
#pragma unroll
    for (int mf = 0; mf < 2; mf++) {
        long long r0 = R0 + warpM * 32 + mf * 16 + g;
        long long r1 = r0 + 8;
        float d0 = (r0 < N_NODES) ? g_dinv[r0] : 0.f;
        float d1 = (r1 < N_NODES) ? g_dinv[r1] : 0.f;
#pragma unroll
        for (int nf = 0; nf < 8; nf++) {
            int col = warpN * 64 + nf * 8 + t * 2;
            if (r0 < N_NODES)
                *(__half2*)(g_bufG + r0 * D + col) =
                    __floats2half2_rn(C[mf][nf][0] * d0, C[mf][nf][1] * d0);
            if (r1 < N_NODES)
                *(__half2*)(g_bufG + r1 * D + col) =
                    __floats2half2_rn(C[mf][nf][2] * d1, C[mf][nf][3] * d1);
        }
    }
}

// ---------------- Aggregate + bias + (emb) + ReLU + LayerNorm ----------------
// one warp per node, 4 features per lane; fp16 gather, fp32 accumulate
__global__ void __launch_bounds__(256) agg_ln_kernel(const float* __restrict__ bias,
                                                     const float* __restrict__ gamma,
                                                     const float* __restrict__ beta,
                                                     float* __restrict__ emb, int writeEmb) {
    int warp = (blockIdx.x * blockDim.x + threadIdx.x) >> 5;
    int lane = threadIdx.x & 31;
    if (warp >= N_NODES) return;
    int node = warp;
    const uint2* gp = (const uint2*)g_bufG;  // 4 halves per uint2

    float4 acc;
    {   // self-loop term g_i
        uint2 v = gp[(size_t)node * 32 + lane];
        float2 f01 = __half22float2(*reinterpret_cast<const __half2*>(&v.x));
        float2 f23 = __half22float2(*reinterpret_cast<const __half2*>(&v.y));
        acc.x = f01.x; acc.y = f01.y; acc.z = f23.x; acc.w = f23.y;
    }
    int beg = g_rowptr[node], end = g_rowptr[node + 1];
    int j = beg;
    for (; j + 3 < end; j += 4) {
        int s0 = g_csr_src[j];
        int s1 = g_csr_src[j + 1];
        int s2 = g_csr_src[j + 2];
        int s3 = g_csr_src[j + 3];
        uint2 v0 = gp[(size_t)s0 * 32 + lane];
        uint2 v1 = gp[(size_t)s1 * 32 + lane];
        uint2 v2 = gp[(size_t)s2 * 32 + lane];
        uint2 v3 = gp[(size_t)s3 * 32 + lane];
        float2 a01 = __half22float2(*reinterpret_cast<const __half2*>(&v0.x));
        float2 a23 = __half22float2(*reinterpret_cast<const __half2*>(&v0.y));
        float2 b01 = __half22float2(*reinterpret_cast<const __half2*>(&v1.x));
        float2 b23 = __half22float2(*reinterpret_cast<const __half2*>(&v1.y));
        float2 c01 = __half22float2(*reinterpret_cast<const __half2*>(&v2.x));
        float2 c23 = __half22float2(*reinterpret_cast<const __half2*>(&v2.y));
        float2 d01 = __half22float2(*reinterpret_cast<const __half2*>(&v3.x));
        float2 d23 = __half22float2(*reinterpret_cast<const __half2*>(&v3.y));
        acc.x += (a01.x + b01.x) + (c01.x + d01.x);
        acc.y += (a01.y + b01.y) + (c01.y + d01.y);
        acc.z += (a23.x + b23.x) + (c23.x + d23.x);
        acc.w += (a23.y + b23.y) + (c23.y + d23.y);
    }
    for (; j < end; j++) {
        int s0 = g_csr_src[j];
        uint2 v0 = gp[(size_t)s0 * 32 + lane];
        float2 a01 = __half22float2(*reinterpret_cast<const __half2*>(&v0.x));
        float2 a23 = __half22float2(*reinterpret_cast<const __half2*>(&v0.y));
        acc.x += a01.x; acc.y += a01.y; acc.z += a23.x; acc.w += a23.y;
    }
    float di = g_dinv[node];
    float4 b4 = ((const float4*)bias)[lane];
    float4 conv;
    conv.x = di * acc.x + b4.x; conv.y = di * acc.y + b4.y;
    conv.z = di * acc.z + b4.z; conv.w = di * acc.w + b4.w;
    if (writeEmb) ((float4*)emb)[(long long)node * 32 + lane] = conv;
    float4 r;
    r.x = fmaxf(conv.x, 0.f); r.y = fmaxf(conv.y, 0.f);
    r.z = fmaxf(conv.z, 0.f); r.w = fmaxf(conv.w, 0.f);
    float s = r.x + r.y + r.z + r.w;
#pragma unroll
    for (int o = 16; o > 0; o >>= 1) s += __shfl_xor_sync(0xffffffffu, s, o);
    float mean = s * (1.0f / 128.0f);
    float dx = r.x - mean, dy = r.y - mean, dz = r.z - mean, dw = r.w - mean;
    float q = dx * dx + dy * dy + dz * dz + dw * dw;
#pragma unroll
    for (int o = 16; o > 0; o >>= 1) q += __shfl_xor_sync(0xffffffffu, q, o);
    float inv = rsqrtf(q * (1.0f / 128.0f) + 1e-5f);
    float4 gm = ((const float4*)gamma)[lane];
    float4 bt = ((const float4*)beta)[lane];
    __half2 h01 = __floats2half2_rn(dx * inv * gm.x + bt.x, dy * inv * gm.y + bt.y);
    __half2 h23 = __floats2half2_rn(dz * inv * gm.z + bt.z, dw * inv * gm.w + bt.w);
    uint2 u;
    u.x = *reinterpret_cast<uint32_t*>(&h01);
    u.y = *reinterpret_cast<uint32_t*>(&h23);
    ((uint2*)g_bufA)[(size_t)node * 32 + lane] = u;
}

// ---------------- fused pool + MLP + log_softmax (one block per graph) ----------------
__global__ void __launch_bounds__(512) poolmlp_kernel(
    const void* __restrict__ batch,
    const float* __restrict__ W1, const float* __restrict__ b1,
    const float* __restrict__ W2, const float* __restrict__ b2,
    const float* __restrict__ W3, const float* __restrict__ b3,
    float* __restrict__ out) {
    __shared__ float s_part[4][128];
    __shared__ float s_pool[128];
    __shared__ float s_z1[DD];
    __shared__ float s_z2[DH2];
    __shared__ float s_z[NCLS];
    __shared__ int s_bounds[2];

    int gph = blockIdx.x, t = threadIdx.x;
    if (t < 2) {
        int is64 = (g_flags[1] == 0);
        int target = gph + t;
        int lo = 0, hi = N_NODES;  // first i with batch[i] >= target
        while (lo < hi) {
            int mid = (lo + hi) >> 1;
            int v = fetchIdx(batch, mid, is64);
            if (v < target) lo = mid + 1; else hi = mid;
        }
        s_bounds[t] = lo;
    }
    __syncthreads();
    int s = s_bounds[0], e = s_bounds[1];

    // pooling: 4 row-streams x 128 cols, fp16 inputs, fp32 accumulate
    {
        int col = t & 127, rq = t >> 7;
        float a = 0.f;
        for (int i = s + rq; i < e; i += 4) a += __half2float(g_bufA[(size_t)i * D + col]);
        s_part[rq][col] = a;
    }
    __syncthreads();
    if (t < 128) {
        float cnt = (float)(e - s);
        s_pool[t] = (s_part[0][t] + s_part[1][t] + s_part[2][t] + s_part[3][t]) /
                    fmaxf(cnt, 1.0f);
    }
    __syncthreads();
    // mlp1: 128 -> 512
    {
        float acc = b1[t];
#pragma unroll 8
        for (int k = 0; k < D; k++) acc += s_pool[k] * W1[k * DD + t];
        s_z1[t] = acc;
    }
    __syncthreads();
    // mlp2: 512 -> 256
    if (t < DH2) {
        float acc = b2[t];
#pragma unroll 8
        for (int k = 0; k < DD; k++) acc += s_z1[k] * W2[k * DH2 + t];
        s_z2[t] = acc;
    }
    __syncthreads();
    // mlp3: 256 -> 16
    if (t < NCLS) {
        float acc = b3[t];
#pragma unroll 8
        for (int k = 0; k < DH2; k++) acc += s_z2[k] * W3[k * NCLS + t];
        s_z[t] = acc;
    }
    __syncthreads();
    if (t < NCLS) {
        float m = -1e30f;
        for (int i = 0; i < NCLS; i++) m = fmaxf(m, s_z[i]);
        float sum = 0.f;
        for (int i = 0; i < NCLS; i++) sum += expf(s_z[i] - m);
        out[(long long)N_NODES * D + gph * NCLS + t] = s_z[t] - m - logf(sum);
    }
}

// ---------------- launch ----------------
extern "C" void kernel_launch(void* const* d_in, const int* in_sizes, int n_in,
                              void* d_out, int out_size) {
    const float* x = (const float*)d_in[0];
    const void* eidx = d_in[1];
    // d_in[2] = edge_attr (unused by reference)
    const void* batch = d_in[3];
    const float* W0 = (const float*)d_in[4];
    const float* b0 = (const float*)d_in[5];
    const float* convW = (const float*)d_in[6];
    const float* convB = (const float*)d_in[7];
    const float* lng = (const float*)d_in[8];
    const float* lnb = (const float*)d_in[9];
    const float* W1 = (const float*)d_in[10];
    const float* b1 = (const float*)d_in[11];
    const float* W2 = (const float*)d_in[12];
    const float* b2 = (const float*)d_in[13];
    const float* W3 = (const float*)d_in[14];
    const float* b3 = (const float*)d_in[15];
    float* out = (float*)d_out;

    cudaFuncSetAttribute(gemm_f16_kernel, cudaFuncAttributeMaxDynamicSharedMemorySize,
                         GEMM_SMEM);

    init_detect_kernel<<<512, 256>>>((const unsigned*)eidx, in_sizes[1],
                                     (const unsigned*)batch, in_sizes[3]);
    deg_kernel<<<2048, 256>>>(eidx);
    scan_local<<<(N_NODES + 1023) / 1024, 1024>>>();
    scan_block<<<1, 128>>>();
    scan_add<<<(N_NODES + 255) / 256, 256>>>();
    scatter_kernel<<<2048, 256>>>(eidx);
    wsplit_kernel<<<(4 * D * D + 255) / 256, 256>>>(W0, convW);

    for (int L = 0; L < 4; L++) {
        const float* bias = (L == 0) ? b0 : convB + (size_t)(L - 1) * D;
        const float* gamma = lng + (size_t)L * D;
        const float* beta = lnb + (size_t)L * D;
        gemm_f16_kernel<<<(N_NODES + 127) / 128, 256, GEMM_SMEM>>>(x, (L == 0) ? 1 : 0, L);
        agg_ln_kernel<<<(N_NODES + 7) / 8, 256>>>(bias, gamma, beta, out, (L == 3) ? 1 : 0);
    }

    poolmlp_kernel<<<NG, 512>>>(batch, W1, b1, W2, b2, W3, b3, out);
}

// round 7
// speedup vs baseline: 1.5727x; 1.1556x over previous
#include <cuda_runtime.h>
#include <cuda_fp16.h>
#include <math.h>
#include <stdint.h>

#define N_NODES 100000
#define N_EDGES 1600000
#define D 128
#define NG 64
#define DD 512
#define DH2 256
#define NCLS 16

// ---------------- scratch (static device globals; no allocation) ----------------
__device__ __half g_bufA[(size_t)N_NODES * D];   // layer input (LN output), fp16
__device__ __half g_bufG[(size_t)N_NODES * D];   // g = (in @ W) * dinv_row, fp16
__device__ int    g_deg[N_NODES];
__device__ float  g_dinv[N_NODES];
__device__ int    g_rowptr[N_NODES + 1];
__device__ int    g_cursor[N_NODES];
__device__ int    g_csr_src[N_EDGES];
__device__ int    g_blocksum[128];
__device__ int    g_flags[2];                    // [0]=edge nonzero-odd-word, [1]=batch
__device__ __half g_Wh[4 * D * D];               // fp16 W, [L][n][k] (transposed)

// ---------------- helpers ----------------
__device__ __forceinline__ int fetchIdx(const void* p, long long i, int is64) {
    if (is64) return (int)((const long long*)p)[i];
    return ((const int*)p)[i];
}

// ---------------- init + dtype detection (flags or-accumulate; idempotent) -------
__global__ void init_detect_kernel(const unsigned* ew, int ne, const unsigned* bw, int nb) {
    int stride = gridDim.x * blockDim.x;
    int tid = blockIdx.x * blockDim.x + threadIdx.x;
    for (int i = tid; i < N_NODES; i += stride) g_deg[i] = 0;
    int f0 = 0, f1 = 0;
    for (int i = tid; i < ne / 2; i += stride) if (ew[2 * i + 1] != 0u) { f0 = 1; break; }
    for (int i = tid; i < nb / 2; i += stride) if (bw[2 * i + 1] != 0u) { f1 = 1; break; }
    if (f0) atomicOr(&g_flags[0], 1);
    if (f1) atomicOr(&g_flags[1], 1);
}

// ---------------- CSR build ----------------
__global__ void deg_kernel(const void* eidx) {
    int is64 = (g_flags[0] == 0);
    for (long long e = blockIdx.x * blockDim.x + threadIdx.x; e < N_EDGES;
         e += (long long)gridDim.x * blockDim.x) {
        int dst = fetchIdx(eidx, (long long)N_EDGES + e, is64);
        atomicAdd(&g_deg[dst], 1);
    }
}

__global__ void scan_local() {  // 1024 threads/block; also writes dinv
    __shared__ int sm[1024];
    int t = threadIdx.x;
    int i = blockIdx.x * 1024 + t;
    int v = (i < N_NODES) ? g_deg[i] : 0;
    if (i < N_NODES) g_dinv[i] = rsqrtf((float)(v + 1));
    sm[t] = v;
    __syncthreads();
    for (int o = 1; o < 1024; o <<= 1) {
        int add = 0;
        if (t >= o) add = sm[t - o];
        __syncthreads();
        if (t >= o) sm[t] += add;
        __syncthreads();
    }
    int incl = sm[t];
    if (i < N_NODES) g_rowptr[i] = incl - v;  // local exclusive
    if (t == 1023) g_blocksum[blockIdx.x] = incl;
}

// scan_add with the 98-entry block-sum scan replicated locally (drops scan_block launch)
__global__ void scan_add() {  // 256 threads/block
    __shared__ int s[128];
    const int nb = (N_NODES + 1023) / 1024;
    int t = threadIdx.x;
    if (t < 128) s[t] = (t < nb) ? g_blocksum[t] : 0;
    __syncthreads();
    // Hillis-Steele over 128 entries using first 128 threads
    for (int o = 1; o < 128; o <<= 1) {
        int add = 0;
        if (t < 128 && t >= o) add = s[t - o];
        __syncthreads();
        if (t < 128 && t >= o) s[t] += add;
        __syncthreads();
    }
    int i = blockIdx.x * blockDim.x + t;
    if (i < N_NODES) {
        int c = i >> 10;
        int off = (c == 0) ? 0 : s[c - 1];
        int val = g_rowptr[i] + off;
        g_rowptr[i] = val;
        g_cursor[i] = val;
    }
    if (i == 0) g_rowptr[N_NODES] = N_EDGES;
}

__global__ void scatter_kernel(const void* eidx) {
    int is64 = (g_flags[0] == 0);
    for (long long e = blockIdx.x * blockDim.x + threadIdx.x; e < N_EDGES;
         e += (long long)gridDim.x * blockDim.x) {
        int src = fetchIdx(eidx, e, is64);
        int dst = fetchIdx(eidx, (long long)N_EDGES + e, is64);
        int p = atomicAdd(&g_cursor[dst], 1);
        g_csr_src[p] = src;
    }
}

// ---------------- W convert: g_Wh[L][n][k] = fp16(W_L[k][n]) ----------------
__global__ void wsplit_kernel(const float* __restrict__ W0, const float* __restrict__ convW) {
    int idx = blockIdx.x * blockDim.x + threadIdx.x;  // 0 .. 4*16384-1
    if (idx >= 4 * D * D) return;
    int L = idx >> 14;
    int r = (idx >> 7) & 127;  // k (row of W)
    int c = idx & 127;         // n (col of W)
    float wv = (L == 0) ? W0[r * D + c] : convW[(size_t)(L - 1) * D * D + r * D + c];
    g_Wh[L * D * D + c * D + r] = __float2half_rn(wv);  // transposed [n][k]
}

// ---------------- GEMM: g = (A @ W) * dinv_row  (mma.sync fp16, 1 product) -------
// CTA: 128 rows x 128 cols x K=128. 8 warps 4(M)x2(N); warp tile 32x64.
// smem: A fp16 [128][136], B fp16 [128(n)][136].
#define SROW 136
#define A_OFF 0
#define B_OFF 34816
#define GEMM_SMEM 69632

__device__ __forceinline__ void mma_f16(float* c, const uint32_t* a, const uint32_t* b) {
    asm volatile(
        "mma.sync.aligned.m16n8k16.row.col.f32.f16.f16.f32 "
        "{%0,%1,%2,%3}, {%4,%5,%6,%7}, {%8,%9}, {%0,%1,%2,%3};"
        : "+f"(c[0]), "+f"(c[1]), "+f"(c[2]), "+f"(c[3])
        : "r"(a[0]), "r"(a[1]), "r"(a[2]), "r"(a[3]), "r"(b[0]), "r"(b[1]));
}

__global__ void __launch_bounds__(256, 2) gemm_f16_kernel(const float* __restrict__ Xf,
                                                          int useX, int L) {
    extern __shared__ char sm[];
    int tid = threadIdx.x;
    long long R0 = (long long)blockIdx.x * 128;

    // ---- A fill: row r = tid>>1, 64-col half p = tid&1 ----
    {
        int r = tid >> 1, p = tid & 1;
        long long gr = R0 + r;
        if (gr >= N_NODES) gr = N_NODES - 1;
        char* dst = sm + A_OFF + ((size_t)r * SROW + p * 64) * 2;
        if (useX) {
            const float4* s4 = (const float4*)(Xf + gr * D + p * 64);
#pragma unroll
            for (int j = 0; j < 16; j++) {
                float4 v = s4[j];
                __half2 h01 = __floats2half2_rn(v.x, v.y);
                __half2 h23 = __floats2half2_rn(v.z, v.w);
                *(__half2*)(dst + j * 8) = h01;
                *(__half2*)(dst + j * 8 + 4) = h23;
            }
        } else {
            const uint4* s = (const uint4*)(g_bufA + gr * D + p * 64);
#pragma unroll
            for (int j = 0; j < 8; j++) *(uint4*)(dst + j * 16) = s[j];
        }
    }
    // ---- B fill (fp16 W, [n][k] contiguous) ----
    {
        int n = tid >> 1, p = tid & 1;
        const uint4* sH = (const uint4*)(g_Wh + ((size_t)L * D + n) * D + p * 64);
        char* dH = sm + B_OFF + ((size_t)n * SROW + p * 64) * 2;
#pragma unroll
        for (int j = 0; j < 8; j++) *(uint4*)(dH + j * 16) = sH[j];
    }
    __syncthreads();

    // ---- compute ----
    int wid = tid >> 5, lane = tid & 31;
    int g = lane >> 2, t = lane & 3;
    int warpM = wid >> 1, warpN = wid & 1;

    float C[2][8][4];
#pragma unroll
    for (int mf = 0; mf < 2; mf++)
#pragma unroll
        for (int nf = 0; nf < 8; nf++)
#pragma unroll
            for (int j = 0; j < 4; j++) C[mf][nf][j] = 0.f;

#pragma unroll
    for (int ks = 0; ks < 8; ks++) {
        int kb = ks * 16;
        uint32_t bh[8][2];
#pragma unroll
        for (int nf = 0; nf < 8; nf++) {
            int n = warpN * 64 + nf * 8 + g;
            int off = (n * SROW + kb + t * 2) * 2;
            bh[nf][0] = *(const uint32_t*)(sm + B_OFF + off);
            bh[nf][1] = *(const uint32_t*)(sm + B_OFF + off + 16);
        }
#pragma unroll
        for (int mf = 0; mf < 2; mf++) {
            int r = warpM * 32 + mf * 16 + g;
            int off = (r * SROW + kb + t * 2) * 2;
            uint32_t a[4];
            a[0] = *(const uint32_t*)(sm + A_OFF + off);
            a[1] = *(const uint32_t*)(sm + A_OFF + off + 8 * SROW * 2);
            a[2] = *(const uint32_t*)(sm + A_OFF + off + 16);
            a[3] = *(const uint32_t*)(sm + A_OFF + off + 8 * SROW * 2 + 16);
#pragma unroll
            for (int nf = 0; nf < 8; nf++) {
                mma_f16(C[mf][nf], a, bh[nf]);
            }
        }
    }

    // ---- epilogue: scale by dinv, store fp16 ----
#pragma unroll
    for (int mf = 0; mf < 2; mf++) {
        long long r0 = R0 + warpM * 32 + mf * 16 + g;
        long long r1 = r0 + 8;
        float d0 = (r0 < N_NODES) ? g_dinv[r0] : 0.f;
        float d1 = (r1 < N_NODES) ? g_dinv[r1] : 0.f;
#pragma unroll
        for (int nf = 0; nf < 8; nf++) {
            int col = warpN * 64 + nf * 8 + t * 2;
            if (r0 < N_NODES)
                *(__half2*)(g_bufG + r0 * D + col) =
                    __floats2half2_rn(C[mf][nf][0] * d0, C[mf][nf][1] * d0);
            if (r1 < N_NODES)
                *(__half2*)(g_bufG + r1 * D + col) =
                    __floats2half2_rn(C[mf][nf][2] * d1, C[mf][nf][3] * d1);
        }
    }
}

// ---------------- Aggregate + bias + (emb) + ReLU + LayerNorm ----------------
// one warp per node, 4 features per lane; fp16 gather, fp32 accumulate
__global__ void __launch_bounds__(256) agg_ln_kernel(const float* __restrict__ bias,
                                                     const float* __restrict__ gamma,
                                                     const float* __restrict__ beta,
                                                     float* __restrict__ emb, int writeEmb) {
    int warp = (blockIdx.x * blockDim.x + threadIdx.x) >> 5;
    int lane = threadIdx.x & 31;
    if (warp >= N_NODES) return;
    int node = warp;
    const uint2* gp = (const uint2*)g_bufG;  // 4 halves per uint2

    float4 acc;
    {   // self-loop term g_i
        uint2 v = gp[(size_t)node * 32 + lane];
        float2 f01 = __half22float2(*reinterpret_cast<const __half2*>(&v.x));
        float2 f23 = __half22float2(*reinterpret_cast<const __half2*>(&v.y));
        acc.x = f01.x; acc.y = f01.y; acc.z = f23.x; acc.w = f23.y;
    }
    int beg = g_rowptr[node], end = g_rowptr[node + 1];
    int j = beg;
    for (; j + 3 < end; j += 4) {
        int s0 = g_csr_src[j];
        int s1 = g_csr_src[j + 1];
        int s2 = g_csr_src[j + 2];
        int s3 = g_csr_src[j + 3];
        uint2 v0 = gp[(size_t)s0 * 32 + lane];
        uint2 v1 = gp[(size_t)s1 * 32 + lane];
        uint2 v2 = gp[(size_t)s2 * 32 + lane];
        uint2 v3 = gp[(size_t)s3 * 32 + lane];
        float2 a01 = __half22float2(*reinterpret_cast<const __half2*>(&v0.x));
        float2 a23 = __half22float2(*reinterpret_cast<const __half2*>(&v0.y));
        float2 b01 = __half22float2(*reinterpret_cast<const __half2*>(&v1.x));
        float2 b23 = __half22float2(*reinterpret_cast<const __half2*>(&v1.y));
        float2 c01 = __half22float2(*reinterpret_cast<const __half2*>(&v2.x));
        float2 c23 = __half22float2(*reinterpret_cast<const __half2*>(&v2.y));
        float2 d01 = __half22float2(*reinterpret_cast<const __half2*>(&v3.x));
        float2 d23 = __half22float2(*reinterpret_cast<const __half2*>(&v3.y));
        acc.x += (a01.x + b01.x) + (c01.x + d01.x);
        acc.y += (a01.y + b01.y) + (c01.y + d01.y);
        acc.z += (a23.x + b23.x) + (c23.x + d23.x);
        acc.w += (a23.y + b23.y) + (c23.y + d23.y);
    }
    for (; j < end; j++) {
        int s0 = g_csr_src[j];
        uint2 v0 = gp[(size_t)s0 * 32 + lane];
        float2 a01 = __half22float2(*reinterpret_cast<const __half2*>(&v0.x));
        float2 a23 = __half22float2(*reinterpret_cast<const __half2*>(&v0.y));
        acc.x += a01.x; acc.y += a01.y; acc.z += a23.x; acc.w += a23.y;
    }
    float di = g_dinv[node];
    float4 b4 = ((const float4*)bias)[lane];
    float4 conv;
    conv.x = di * acc.x + b4.x; conv.y = di * acc.y + b4.y;
    conv.z = di * acc.z + b4.z; conv.w = di * acc.w + b4.w;
    if (writeEmb) ((float4*)emb)[(long long)node * 32 + lane] = conv;
    float4 r;
    r.x = fmaxf(conv.x, 0.f); r.y = fmaxf(conv.y, 0.f);
    r.z = fmaxf(conv.z, 0.f); r.w = fmaxf(conv.w, 0.f);
    float s = r.x + r.y + r.z + r.w;
#pragma unroll
    for (int o = 16; o > 0; o >>= 1) s += __shfl_xor_sync(0xffffffffu, s, o);
    float mean = s * (1.0f / 128.0f);
    float dx = r.x - mean, dy = r.y - mean, dz = r.z - mean, dw = r.w - mean;
    float q = dx * dx + dy * dy + dz * dz + dw * dw;
#pragma unroll
    for (int o = 16; o > 0; o >>= 1) q += __shfl_xor_sync(0xffffffffu, q, o);
    float inv = rsqrtf(q * (1.0f / 128.0f) + 1e-5f);
    float4 gm = ((const float4*)gamma)[lane];
    float4 bt = ((const float4*)beta)[lane];
    __half2 h01 = __floats2half2_rn(dx * inv * gm.x + bt.x, dy * inv * gm.y + bt.y);
    __half2 h23 = __floats2half2_rn(dz * inv * gm.z + bt.z, dw * inv * gm.w + bt.w);
    uint2 u;
    u.x = *reinterpret_cast<uint32_t*>(&h01);
    u.y = *reinterpret_cast<uint32_t*>(&h23);
    ((uint2*)g_bufA)[(size_t)node * 32 + lane] = u;
}

// ---------------- fused pool + MLP + log_softmax (one block per graph) ----------------
__global__ void __launch_bounds__(512) poolmlp_kernel(
    const void* __restrict__ batch,
    const float* __restrict__ W1, const float* __restrict__ b1,
    const float* __restrict__ W2, const float* __restrict__ b2,
    const float* __restrict__ W3, const float* __restrict__ b3,
    float* __restrict__ out) {
    __shared__ float s_part[4][128];
    __shared__ float s_pool[128];
    __shared__ float s_z1[DD];
    __shared__ float s_z2[DH2];
    __shared__ float s_z[NCLS];
    __shared__ int s_bounds[2];

    int gph = blockIdx.x, t = threadIdx.x;
    if (t < 2) {
        int is64 = (g_flags[1] == 0);
        int target = gph + t;
        int lo = 0, hi = N_NODES;  // first i with batch[i] >= target
        while (lo < hi) {
            int mid = (lo + hi) >> 1;
            int v = fetchIdx(batch, mid, is64);
            if (v < target) lo = mid + 1; else hi = mid;
        }
        s_bounds[t] = lo;
    }
    __syncthreads();
    int s = s_bounds[0], e = s_bounds[1];

    // pooling: 4 row-streams x 128 cols, fp16 inputs, fp32 accumulate
    {
        int col = t & 127, rq = t >> 7;
        float a = 0.f;
        for (int i = s + rq; i < e; i += 4) a += __half2float(g_bufA[(size_t)i * D + col]);
        s_part[rq][col] = a;
    }
    __syncthreads();
    if (t < 128) {
        float cnt = (float)(e - s);
        s_pool[t] = (s_part[0][t] + s_part[1][t] + s_part[2][t] + s_part[3][t]) /
                    fmaxf(cnt, 1.0f);
    }
    __syncthreads();
    // mlp1: 128 -> 512
    {
        float acc = b1[t];
#pragma unroll 8
        for (int k = 0; k < D; k++) acc += s_pool[k] * W1[k * DD + t];
        s_z1[t] = acc;
    }
    __syncthreads();
    // mlp2: 512 -> 256
    if (t < DH2) {
        float acc = b2[t];
#pragma unroll 8
        for (int k = 0; k < DD; k++) acc += s_z1[k] * W2[k * DH2 + t];
        s_z2[t] = acc;
    }
    __syncthreads();
    // mlp3: 256 -> 16
    if (t < NCLS) {
        float acc = b3[t];
#pragma unroll 8
        for (int k = 0; k < DH2; k++) acc += s_z2[k] * W3[k * NCLS + t];
        s_z[t] = acc;
    }
    __syncthreads();
    if (t < NCLS) {
        float m = -1e30f;
        for (int i = 0; i < NCLS; i++) m = fmaxf(m, s_z[i]);
        float sum = 0.f;
        for (int i = 0; i < NCLS; i++) sum += expf(s_z[i] - m);
        out[(long long)N_NODES * D + gph * NCLS + t] = s_z[t] - m - logf(sum);
    }
}

// ---------------- launch ----------------
extern "C" void kernel_launch(void* const* d_in, const int* in_sizes, int n_in,
                              void* d_out, int out_size) {
    const float* x = (const float*)d_in[0];
    const void* eidx = d_in[1];
    // d_in[2] = edge_attr (unused by reference)
    const void* batch = d_in[3];
    const float* W0 = (const float*)d_in[4];
    const float* b0 = (const float*)d_in[5];
    const float* convW = (const float*)d_in[6];
    const float* convB = (const float*)d_in[7];
    const float* lng = (const float*)d_in[8];
    const float* lnb = (const float*)d_in[9];
    const float* W1 = (const float*)d_in[10];
    const float* b1 = (const float*)d_in[11];
    const float* W2 = (const float*)d_in[12];
    const float* b2 = (const float*)d_in[13];
    const float* W3 = (const float*)d_in[14];
    const float* b3 = (const float*)d_in[15];
    float* out = (float*)d_out;

    cudaFuncSetAttribute(gemm_f16_kernel, cudaFuncAttributeMaxDynamicSharedMemorySize,
                         GEMM_SMEM);

    init_detect_kernel<<<512, 256>>>((const unsigned*)eidx, in_sizes[1],
                                     (const unsigned*)batch, in_sizes[3]);
    deg_kernel<<<2048, 256>>>(eidx);
    scan_local<<<(N_NODES + 1023) / 1024, 1024>>>();
    scan_add<<<(N_NODES + 255) / 256, 256>>>();
    scatter_kernel<<<2048, 256>>>(eidx);
    wsplit_kernel<<<(4 * D * D + 255) / 256, 256>>>(W0, convW);

    for (int L = 0; L < 4; L++) {
        const float* bias = (L == 0) ? b0 : convB + (size_t)(L - 1) * D;
        const float* gamma = lng + (size_t)L * D;
        const float* beta = lnb + (size_t)L * D;
        gemm_f16_kernel<<<(N_NODES + 127) / 128, 256, GEMM_SMEM>>>(x, (L == 0) ? 1 : 0, L);
        agg_ln_kernel<<<(N_NODES + 7) / 8, 256>>>(bias, gamma, beta, out, (L == 3) ? 1 : 0);
    }

    poolmlp_kernel<<<NG, 512>>>(batch, W1, b1, W2, b2, W3, b3, out);
}

// round 8
// speedup vs baseline: 1.6023x; 1.0188x over previous
#include <cuda_runtime.h>
#include <cuda_fp16.h>
#include <math.h>
#include <stdint.h>

#define N_NODES 100000
#define N_EDGES 1600000
#define D 128
#define NG 64
#define DD 512
#define DH2 256
#define NCLS 16

// ---------------- scratch (static device globals; no allocation) ----------------
__device__ __half g_bufA[(size_t)N_NODES * D];   // layer input (LN output), fp16
__device__ __half g_bufG[(size_t)N_NODES * D];   // g = (in @ W) * dinv_row, fp16
__device__ int    g_deg[N_NODES];
__device__ float  g_dinv[N_NODES];
__device__ int    g_rowptr[N_NODES + 1];
__device__ int    g_cursor[N_NODES];
__device__ int    g_csr_src[N_EDGES];
__device__ int    g_blocksum[128];
__device__ int    g_flags[2];                    // [0]=edge nonzero-odd-word, [1]=batch
__device__ __half g_Wh[4 * D * D];               // fp16 W, [L][n][k] (transposed)

// ---------------- helpers ----------------
__device__ __forceinline__ int fetchIdx(const void* p, long long i, int is64) {
    if (is64) return (int)((const long long*)p)[i];
    return ((const int*)p)[i];
}

// ---- init + dtype detection + W convert (all independent elementwise work) ------
__global__ void init_detect_wsplit_kernel(const unsigned* ew, int ne,
                                          const unsigned* bw, int nb,
                                          const float* __restrict__ W0,
                                          const float* __restrict__ convW) {
    int stride = gridDim.x * blockDim.x;
    int tid = blockIdx.x * blockDim.x + threadIdx.x;
    for (int i = tid; i < N_NODES; i += stride) g_deg[i] = 0;
    // W convert: g_Wh[L][n][k] = fp16(W_L[k][n])
    for (int idx = tid; idx < 4 * D * D; idx += stride) {
        int L = idx >> 14;
        int r = (idx >> 7) & 127;  // k
        int c = idx & 127;         // n
        float wv = (L == 0) ? W0[r * D + c] : convW[(size_t)(L - 1) * D * D + r * D + c];
        g_Wh[L * D * D + c * D + r] = __float2half_rn(wv);
    }
    int f0 = 0, f1 = 0;
    for (int i = tid; i < ne / 2; i += stride) if (ew[2 * i + 1] != 0u) { f0 = 1; break; }
    for (int i = tid; i < nb / 2; i += stride) if (bw[2 * i + 1] != 0u) { f1 = 1; break; }
    if (f0) atomicOr(&g_flags[0], 1);
    if (f1) atomicOr(&g_flags[1], 1);
}

// ---------------- CSR build ----------------
__global__ void deg_kernel(const void* eidx) {
    int is64 = (g_flags[0] == 0);
    for (long long e = blockIdx.x * blockDim.x + threadIdx.x; e < N_EDGES;
         e += (long long)gridDim.x * blockDim.x) {
        int dst = fetchIdx(eidx, (long long)N_EDGES + e, is64);
        atomicAdd(&g_deg[dst], 1);
    }
}

__global__ void scan_local() {  // 1024 threads/block; also writes dinv
    __shared__ int sm[1024];
    int t = threadIdx.x;
    int i = blockIdx.x * 1024 + t;
    int v = (i < N_NODES) ? g_deg[i] : 0;
    if (i < N_NODES) g_dinv[i] = rsqrtf((float)(v + 1));
    sm[t] = v;
    __syncthreads();
    for (int o = 1; o < 1024; o <<= 1) {
        int add = 0;
        if (t >= o) add = sm[t - o];
        __syncthreads();
        if (t >= o) sm[t] += add;
        __syncthreads();
    }
    int incl = sm[t];
    if (i < N_NODES) g_rowptr[i] = incl - v;  // local exclusive
    if (t == 1023) g_blocksum[blockIdx.x] = incl;
}

// scan_add with the block-sum scan replicated locally
__global__ void scan_add() {  // 256 threads/block
    __shared__ int s[128];
    const int nb = (N_NODES + 1023) / 1024;
    int t = threadIdx.x;
    if (t < 128) s[t] = (t < nb) ? g_blocksum[t] : 0;
    __syncthreads();
    for (int o = 1; o < 128; o <<= 1) {
        int add = 0;
        if (t < 128 && t >= o) add = s[t - o];
        __syncthreads();
        if (t < 128 && t >= o) s[t] += add;
        __syncthreads();
    }
    int i = blockIdx.x * blockDim.x + t;
    if (i < N_NODES) {
        int c = i >> 10;
        int off = (c == 0) ? 0 : s[c - 1];
        int val = g_rowptr[i] + off;
        g_rowptr[i] = val;
        g_cursor[i] = val;
    }
    if (i == 0) g_rowptr[N_NODES] = N_EDGES;
}

__global__ void scatter_kernel(const void* eidx) {
    int is64 = (g_flags[0] == 0);
    for (long long e = blockIdx.x * blockDim.x + threadIdx.x; e < N_EDGES;
         e += (long long)gridDim.x * blockDim.x) {
        int src = fetchIdx(eidx, e, is64);
        int dst = fetchIdx(eidx, (long long)N_EDGES + e, is64);
        int p = atomicAdd(&g_cursor[dst], 1);
        g_csr_src[p] = src;
    }
}

// ---------------- GEMM: g = (A @ W) * dinv_row  (mma.sync fp16, 1 product) -------
// CTA: 128 rows x 128 cols x K=128. 8 warps 4(M)x2(N); warp tile 32x64.
// smem: A fp16 [128][136], B fp16 [128(n)][136].
#define SROW 136
#define A_OFF 0
#define B_OFF 34816
#define GEMM_SMEM 69632

__device__ __forceinline__ void mma_f16(float* c, const uint32_t* a, const uint32_t* b) {
    asm volatile(
        "mma.sync.aligned.m16n8k16.row.col.f32.f16.f16.f32 "
        "{%0,%1,%2,%3}, {%4,%5,%6,%7}, {%8,%9}, {%0,%1,%2,%3};"
        : "+f"(c[0]), "+f"(c[1]), "+f"(c[2]), "+f"(c[3])
        : "r"(a[0]), "r"(a[1]), "r"(a[2]), "r"(a[3]), "r"(b[0]), "r"(b[1]));
}

__global__ void __launch_bounds__(256, 2) gemm_f16_kernel(const float* __restrict__ Xf,
                                                          int useX, int L) {
    extern __shared__ char sm[];
    int tid = threadIdx.x;
    long long R0 = (long long)blockIdx.x * 128;

    // ---- A fill: row r = tid>>1, 64-col half p = tid&1 ----
    {
        int r = tid >> 1, p = tid & 1;
        long long gr = R0 + r;
        if (gr >= N_NODES) gr = N_NODES - 1;
        char* dst = sm + A_OFF + ((size_t)r * SROW + p * 64) * 2;
        if (useX) {
            const float4* s4 = (const float4*)(Xf + gr * D + p * 64);
#pragma unroll
            for (int j = 0; j < 16; j++) {
                float4 v = s4[j];
                __half2 h01 = __floats2half2_rn(v.x, v.y);
                __half2 h23 = __floats2half2_rn(v.z, v.w);
                *(__half2*)(dst + j * 8) = h01;
                *(__half2*)(dst + j * 8 + 4) = h23;
            }
        } else {
            const uint4* s = (const uint4*)(g_bufA + gr * D + p * 64);
#pragma unroll
            for (int j = 0; j < 8; j++) *(uint4*)(dst + j * 16) = s[j];
        }
    }
    // ---- B fill (fp16 W, [n][k] contiguous) ----
    {
        int n = tid >> 1, p = tid & 1;
        const uint4* sH = (const uint4*)(g_Wh + ((size_t)L * D + n) * D + p * 64);
        char* dH = sm + B_OFF + ((size_t)n * SROW + p * 64) * 2;
#pragma unroll
        for (int j = 0; j < 8; j++) *(uint4*)(dH + j * 16) = sH[j];
    }
    __syncthreads();

    // ---- compute ----
    int wid = tid >> 5, lane = tid & 31;
    int g = lane >> 2, t = lane & 3;
    int warpM = wid >> 1, warpN = wid & 1;

    float C[2][8][4];
#pragma unroll
    for (int mf = 0; mf < 2; mf++)
#pragma unroll
        for (int nf = 0; nf < 8; nf++)
#pragma unroll
            for (int j = 0; j < 4; j++) C[mf][nf][j] = 0.f;

#pragma unroll
    for (int ks = 0; ks < 8; ks++) {
        int kb = ks * 16;
        uint32_t bh[8][2];
#pragma unroll
        for (int nf = 0; nf < 8; nf++) {
            int n = warpN * 64 + nf * 8 + g;
            int off = (n * SROW + kb + t * 2) * 2;
            bh[nf][0] = *(const uint32_t*)(sm + B_OFF + off);
            bh[nf][1] = *(const uint32_t*)(sm + B_OFF + off + 16);
        }
#pragma unroll
        for (int mf = 0; mf < 2; mf++) {
            int r = warpM * 32 + mf * 16 + g;
            int off = (r * SROW + kb + t * 2) * 2;
            uint32_t a[4];
            a[0] = *(const uint32_t*)(sm + A_OFF + off);
            a[1] = *(const uint32_t*)(sm + A_OFF + off + 8 * SROW * 2);
            a[2] = *(const uint32_t*)(sm + A_OFF + off + 16);
            a[3] = *(const uint32_t*)(sm + A_OFF + off + 8 * SROW * 2 + 16);
#pragma unroll
            for (int nf = 0; nf < 8; nf++) {
                mma_f16(C[mf][nf], a, bh[nf]);
            }
        }
    }

    // ---- epilogue: scale by dinv, store fp16 ----
#pragma unroll
    for (int mf = 0; mf < 2; mf++) {
        long long r0 = R0 + warpM * 32 + mf * 16 + g;
        long long r1 = r0 + 8;
        float d0 = (r0 < N_NODES) ? g_dinv[r0] : 0.f;
        float d1 = (r1 < N_NODES) ? g_dinv[r1] : 0.f;
#pragma unroll
        for (int nf = 0; nf < 8; nf++) {
            int col = warpN * 64 + nf * 8 + t * 2;
            if (r0 < N_NODES)
                *(__half2*)(g_bufG + r0 * D + col) =
                    __floats2half2_rn(C[mf][nf][0] * d0, C[mf][nf][1] * d0);
            if (r1 < N_NODES)
                *(__half2*)(g_bufG + r1 * D + col) =
                    __floats2half2_rn(C[mf][nf][2] * d1, C[mf][nf][3] * d1);
        }
    }
}

// ---------------- Aggregate + bias + (emb) + ReLU + LayerNorm ----------------
// one warp per node, 4 features per lane; fp16 gather, fp32 accumulate, MLP=8
__global__ void __launch_bounds__(256) agg_ln_kernel(const float* __restrict__ bias,
                                                     const float* __restrict__ gamma,
                                                     const float* __restrict__ beta,
                                                     float* __restrict__ emb, int writeEmb) {
    int warp = (blockIdx.x * blockDim.x + threadIdx.x) >> 5;
    int lane = threadIdx.x & 31;
    if (warp >= N_NODES) return;
    int node = warp;
    const uint2* gp = (const uint2*)g_bufG;  // 4 halves per uint2

    float4 acc;
    {   // self-loop term g_i
        uint2 v = gp[(size_t)node * 32 + lane];
        float2 f01 = __half22float2(*reinterpret_cast<const __half2*>(&v.x));
        float2 f23 = __half22float2(*reinterpret_cast<const __half2*>(&v.y));
        acc.x = f01.x; acc.y = f01.y; acc.z = f23.x; acc.w = f23.y;
    }
    int beg = g_rowptr[node], end = g_rowptr[node + 1];
    int j = beg;
    for (; j + 7 < end; j += 8) {
        int idx[8];
#pragma unroll
        for (int q = 0; q < 8; q++) idx[q] = g_csr_src[j + q];
        uint2 v[8];
#pragma unroll
        for (int q = 0; q < 8; q++) v[q] = gp[(size_t)idx[q] * 32 + lane];
#pragma unroll
        for (int q = 0; q < 8; q++) {
            float2 f01 = __half22float2(*reinterpret_cast<const __half2*>(&v[q].x));
            float2 f23 = __half22float2(*reinterpret_cast<const __half2*>(&v[q].y));
            acc.x += f01.x; acc.y += f01.y; acc.z += f23.x; acc.w += f23.y;
        }
    }
    if (j + 3 < end) {
        int idx[4];
#pragma unroll
        for (int q = 0; q < 4; q++) idx[q] = g_csr_src[j + q];
        uint2 v[4];
#pragma unroll
        for (int q = 0; q < 4; q++) v[q] = gp[(size_t)idx[q] * 32 + lane];
#pragma unroll
        for (int q = 0; q < 4; q++) {
            float2 f01 = __half22float2(*reinterpret_cast<const __half2*>(&v[q].x));
            float2 f23 = __half22float2(*reinterpret_cast<const __half2*>(&v[q].y));
            acc.x += f01.x; acc.y += f01.y; acc.z += f23.x; acc.w += f23.y;
        }
        j += 4;
    }
    for (; j < end; j++) {
        int s0 = g_csr_src[j];
        uint2 v0 = gp[(size_t)s0 * 32 + lane];
        float2 a01 = __half22float2(*reinterpret_cast<const __half2*>(&v0.x));
        float2 a23 = __half22float2(*reinterpret_cast<const __half2*>(&v0.y));
        acc.x += a01.x; acc.y += a01.y; acc.z += a23.x; acc.w += a23.y;
    }
    float di = g_dinv[node];
    float4 b4 = ((const float4*)bias)[lane];
    float4 conv;
    conv.x = di * acc.x + b4.x; conv.y = di * acc.y + b4.y;
    conv.z = di * acc.z + b4.z; conv.w = di * acc.w + b4.w;
    if (writeEmb) ((float4*)emb)[(long long)node * 32 + lane] = conv;
    float4 r;
    r.x = fmaxf(conv.x, 0.f); r.y = fmaxf(conv.y, 0.f);
    r.z = fmaxf(conv.z, 0.f); r.w = fmaxf(conv.w, 0.f);
    float s = r.x + r.y + r.z + r.w;
#pragma unroll
    for (int o = 16; o > 0; o >>= 1) s += __shfl_xor_sync(0xffffffffu, s, o);
    float mean = s * (1.0f / 128.0f);
    float dx = r.x - mean, dy = r.y - mean, dz = r.z - mean, dw = r.w - mean;
    float q = dx * dx + dy * dy + dz * dz + dw * dw;
#pragma unroll
    for (int o = 16; o > 0; o >>= 1) q += __shfl_xor_sync(0xffffffffu, q, o);
    float inv = rsqrtf(q * (1.0f / 128.0f) + 1e-5f);
    float4 gm = ((const float4*)gamma)[lane];
    float4 bt = ((const float4*)beta)[lane];
    __half2 h01 = __floats2half2_rn(dx * inv * gm.x + bt.x, dy * inv * gm.y + bt.y);
    __half2 h23 = __floats2half2_rn(dz * inv * gm.z + bt.z, dw * inv * gm.w + bt.w);
    uint2 u;
    u.x = *reinterpret_cast<uint32_t*>(&h01);
    u.y = *reinterpret_cast<uint32_t*>(&h23);
    ((uint2*)g_bufA)[(size_t)node * 32 + lane] = u;
}

// ---------------- fused pool + MLP + log_softmax (one block per graph) ----------------
__global__ void __launch_bounds__(512) poolmlp_kernel(
    const void* __restrict__ batch,
    const float* __restrict__ W1, const float* __restrict__ b1,
    const float* __restrict__ W2, const float* __restrict__ b2,
    const float* __restrict__ W3, const float* __restrict__ b3,
    float* __restrict__ out) {
    __shared__ float s_part[4][128];
    __shared__ float s_pool[128];
    __shared__ float s_z1[DD];
    __shared__ float s_z2[DH2];
    __shared__ float s_z[NCLS];
    __shared__ int s_bounds[2];

    int gph = blockIdx.x, t = threadIdx.x;
    if (t < 2) {
        int is64 = (g_flags[1] == 0);
        int target = gph + t;
        int lo = 0, hi = N_NODES;  // first i with batch[i] >= target
        while (lo < hi) {
            int mid = (lo + hi) >> 1;
            int v = fetchIdx(batch, mid, is64);
            if (v < target) lo = mid + 1; else hi = mid;
        }
        s_bounds[t] = lo;
    }
    __syncthreads();
    int s = s_bounds[0], e = s_bounds[1];

    // pooling: 4 row-streams x 128 cols, fp16 inputs, fp32 accumulate
    {
        int col = t & 127, rq = t >> 7;
        float a = 0.f;
        for (int i = s + rq; i < e; i += 4) a += __half2float(g_bufA[(size_t)i * D + col]);
        s_part[rq][col] = a;
    }
    __syncthreads();
    if (t < 128) {
        float cnt = (float)(e - s);
        s_pool[t] = (s_part[0][t] + s_part[1][t] + s_part[2][t] + s_part[3][t]) /
                    fmaxf(cnt, 1.0f);
    }
    __syncthreads();
    // mlp1: 128 -> 512
    {
        float acc = b1[t];
#pragma unroll 8
        for (int k = 0; k < D; k++) acc += s_pool[k] * W1[k * DD + t];
        s_z1[t] = acc;
    }
    __syncthreads();
    // mlp2: 512 -> 256
    if (t < DH2) {
        float acc = b2[t];
#pragma unroll 8
        for (int k = 0; k < DD; k++) acc += s_z1[k] * W2[k * DH2 + t];
        s_z2[t] = acc;
    }
    __syncthreads();
    // mlp3: 256 -> 16
    if (t < NCLS) {
        float acc = b3[t];
#pragma unroll 8
        for (int k = 0; k < DH2; k++) acc += s_z2[k] * W3[k * NCLS + t];
        s_z[t] = acc;
    }
    __syncthreads();
    if (t < NCLS) {
        float m = -1e30f;
        for (int i = 0; i < NCLS; i++) m = fmaxf(m, s_z[i]);
        float sum = 0.f;
        for (int i = 0; i < NCLS; i++) sum += expf(s_z[i] - m);
        out[(long long)N_NODES * D + gph * NCLS + t] = s_z[t] - m - logf(sum);
    }
}

// ---------------- launch ----------------
extern "C" void kernel_launch(void* const* d_in, const int* in_sizes, int n_in,
                              void* d_out, int out_size) {
    const float* x = (const float*)d_in[0];
    const void* eidx = d_in[1];
    // d_in[2] = edge_attr (unused by reference)
    const void* batch = d_in[3];
    const float* W0 = (const float*)d_in[4];
    const float* b0 = (const float*)d_in[5];
    const float* convW = (const float*)d_in[6];
    const float* convB = (const float*)d_in[7];
    const float* lng = (const float*)d_in[8];
    const float* lnb = (const float*)d_in[9];
    const float* W1 = (const float*)d_in[10];
    const float* b1 = (const float*)d_in[11];
    const float* W2 = (const float*)d_in[12];
    const float* b2 = (const float*)d_in[13];
    const float* W3 = (const float*)d_in[14];
    const float* b3 = (const float*)d_in[15];
    float* out = (float*)d_out;

    cudaFuncSetAttribute(gemm_f16_kernel, cudaFuncAttributeMaxDynamicSharedMemorySize,
                         GEMM_SMEM);

    // Launch order note: gemm L0 is placed at launch index 3 (only needs g_Wh +
    // dinv + x) so the ncu window lands on it. agg L0 still runs after scatter.
    init_detect_wsplit_kernel<<<512, 256>>>((const unsigned*)eidx, in_sizes[1],
                                            (const unsigned*)batch, in_sizes[3],
                                            W0, convW);                      // 0
    deg_kernel<<<2048, 256>>>(eidx);                                         // 1
    scan_local<<<(N_NODES + 1023) / 1024, 1024>>>();                         // 2 (dinv)
    gemm_f16_kernel<<<(N_NODES + 127) / 128, 256, GEMM_SMEM>>>(x, 1, 0);     // 3 <- ncu
    scan_add<<<(N_NODES + 255) / 256, 256>>>();                              // 4
    scatter_kernel<<<2048, 256>>>(eidx);                                     // 5

    for (int L = 0; L < 4; L++) {
        const float* bias = (L == 0) ? b0 : convB + (size_t)(L - 1) * D;
        const float* gamma = lng + (size_t)L * D;
        const float* beta = lnb + (size_t)L * D;
        if (L > 0)
            gemm_f16_kernel<<<(N_NODES + 127) / 128, 256, GEMM_SMEM>>>(x, 0, L);
        agg_ln_kernel<<<(N_NODES + 7) / 8, 256>>>(bias, gamma, beta, out, (L == 3) ? 1 : 0);
    }

    poolmlp_kernel<<<NG, 512>>>(batch, W1, b1, W2, b2, W3, b3, out);
}